// round 1
// baseline (speedup 1.0000x reference)
#include <cuda_runtime.h>
#include <math.h>

#define BB 2
#define SS 4096
#define DD 768
#define HH 12
#define DHH 64
#define W1C 256
#define NCC 16
#define MTOK (BB*SS)   // 8192

// ---------------- scratch (device globals; no allocation allowed) ----------------
__device__ float g_x  [MTOK*DD];
__device__ float g_q  [MTOK*DD];
__device__ float g_k  [MTOK*DD];
__device__ float g_v  [MTOK*DD];
__device__ float g_ctx[MTOK*DD];
__device__ float g_h  [MTOK*DD];

// ---------------- block reduction: sum + sumsq over 256 threads ----------------
__device__ __forceinline__ void block_reduce2(float& s, float& s2) {
    __shared__ float r1[8], r2[8];
    const unsigned mask = 0xffffffffu;
    #pragma unroll
    for (int o = 16; o > 0; o >>= 1) {
        s  += __shfl_xor_sync(mask, s,  o);
        s2 += __shfl_xor_sync(mask, s2, o);
    }
    int w = threadIdx.x >> 5, lane = threadIdx.x & 31;
    if (lane == 0) { r1[w] = s; r2[w] = s2; }
    __syncthreads();
    float a = 0.f, b = 0.f;
    #pragma unroll
    for (int i = 0; i < 8; i++) { a += r1[i]; b += r2[i]; }
    s = a; s2 = b;
}

// ---------------- embedding gather + layernorm ----------------
__global__ __launch_bounds__(256) void embed_ln_kernel(
    const int* __restrict__ ids, const float* __restrict__ wemb,
    const float* __restrict__ pemb, const float* __restrict__ g,
    const float* __restrict__ b, float* __restrict__ x)
{
    int tok = blockIdx.x;
    int s_pos = tok & (SS - 1);
    int id = ids[tok];
    const float* we = wemb + (size_t)id * DD;
    const float* pe = pemb + (size_t)s_pos * DD;
    float v[3]; float sum = 0.f, sum2 = 0.f;
    #pragma unroll
    for (int i = 0; i < 3; i++) {
        int d = threadIdx.x + i * 256;
        v[i] = we[d] + pe[d];
        sum += v[i]; sum2 += v[i] * v[i];
    }
    block_reduce2(sum, sum2);
    float mean = sum * (1.0f / DD);
    float var  = sum2 * (1.0f / DD) - mean * mean;
    float rstd = rsqrtf(var + 1e-5f);
    float* row = x + (size_t)tok * DD;
    #pragma unroll
    for (int i = 0; i < 3; i++) {
        int d = threadIdx.x + i * 256;
        row[d] = (v[i] - mean) * rstd * g[d] + b[d];
    }
}

// ---------------- final layernorm ----------------
__global__ __launch_bounds__(256) void ln_kernel(
    const float* __restrict__ in, const float* __restrict__ g,
    const float* __restrict__ b, float* __restrict__ out)
{
    int tok = blockIdx.x;
    const float* row = in + (size_t)tok * DD;
    float v[3]; float sum = 0.f, sum2 = 0.f;
    #pragma unroll
    for (int i = 0; i < 3; i++) {
        int d = threadIdx.x + i * 256;
        v[i] = row[d];
        sum += v[i]; sum2 += v[i] * v[i];
    }
    block_reduce2(sum, sum2);
    float mean = sum * (1.0f / DD);
    float var  = sum2 * (1.0f / DD) - mean * mean;
    float rstd = rsqrtf(var + 1e-5f);
    float* orow = out + (size_t)tok * DD;
    #pragma unroll
    for (int i = 0; i < 3; i++) {
        int d = threadIdx.x + i * 256;
        orow[d] = (v[i] - mean) * rstd * g[d] + b[d];
    }
}

// ---------------- fp32 tiled GEMM: C[M,768] = A[M,768] @ W[768,768] + bias (+res) ----------------
#define BM 64
#define BN 64
#define BK 16

template<bool RES>
__global__ __launch_bounds__(256) void gemm_kernel(
    const float* __restrict__ A, const float* __restrict__ Wt,
    const float* __restrict__ bias, const float* __restrict__ res,
    float* __restrict__ C)
{
    __shared__ float As[BK][BM];
    __shared__ float Bs[BK][BN];
    int tid = threadIdx.x;
    int tx = tid & 15, ty = tid >> 4;
    int rowBase = blockIdx.y * BM;
    int colBase = blockIdx.x * BN;
    int am = tid >> 2, ak = (tid & 3) << 2;
    int bkr = tid >> 4, bn = (tid & 15) << 2;

    float acc[4][4] = {};
    for (int k0 = 0; k0 < DD; k0 += BK) {
        float4 a4 = *(const float4*)&A[(size_t)(rowBase + am) * DD + k0 + ak];
        As[ak + 0][am] = a4.x; As[ak + 1][am] = a4.y;
        As[ak + 2][am] = a4.z; As[ak + 3][am] = a4.w;
        float4 b4 = *(const float4*)&Wt[(size_t)(k0 + bkr) * DD + colBase + bn];
        *(float4*)&Bs[bkr][bn] = b4;
        __syncthreads();
        #pragma unroll
        for (int kk = 0; kk < BK; kk++) {
            float4 av = *(const float4*)&As[kk][ty << 2];
            float4 bv = *(const float4*)&Bs[kk][tx << 2];
            float ar[4] = {av.x, av.y, av.z, av.w};
            float br[4] = {bv.x, bv.y, bv.z, bv.w};
            #pragma unroll
            for (int i = 0; i < 4; i++)
                #pragma unroll
                for (int j = 0; j < 4; j++)
                    acc[i][j] += ar[i] * br[j];
        }
        __syncthreads();
    }
    int col0 = colBase + (tx << 2);
    float4 bi = *(const float4*)&bias[col0];
    #pragma unroll
    for (int i = 0; i < 4; i++) {
        int row = rowBase + (ty << 2) + i;
        float4 o;
        o.x = acc[i][0] + bi.x;
        o.y = acc[i][1] + bi.y;
        o.z = acc[i][2] + bi.z;
        o.w = acc[i][3] + bi.w;
        if (RES) {
            float4 r4 = *(const float4*)&res[(size_t)row * DD + col0];
            o.x += r4.x; o.y += r4.y; o.z += r4.z; o.w += r4.w;
        }
        *(float4*)&C[(size_t)row * DD + col0] = o;
    }
}

// ---------------- banded attention ----------------
// grid (NC, H, B); 256 threads; thread t handles query row t of the chunk.
#define KCH 64   // keys per smem chunk

__global__ __launch_bounds__(256, 1) void attn_kernel(
    const float* __restrict__ q, const float* __restrict__ k,
    const float* __restrict__ v, float* __restrict__ ctx)
{
    __shared__ float4 ks[KCH][16];
    __shared__ float4 vs[KCH][16];

    int c = blockIdx.x, h = blockIdx.y, b = blockIdx.z;
    int qi = threadIdx.x;
    int qrow = b * SS + c * W1C + qi;
    const float scale = 0.125f;   // 64^-0.5

    float qr[64];
    {
        const float4* qp = (const float4*)(q + (size_t)qrow * DD + h * DHH);
        #pragma unroll
        for (int i = 0; i < 16; i++) {
            float4 t = qp[i];
            qr[4*i+0] = t.x * scale; qr[4*i+1] = t.y * scale;
            qr[4*i+2] = t.z * scale; qr[4*i+3] = t.w * scale;
        }
    }
    float acc[64];
    #pragma unroll
    for (int d = 0; d < 64; d++) acc[d] = 0.f;
    float m = -INFINITY, l = 0.f;

    int kbase = c * W1C - W1C;   // global key row for j=0

    for (int kc = 0; kc < (3 * W1C) / KCH; kc++) {
        // cooperative load of KCH key rows + value rows into smem
        #pragma unroll
        for (int i = 0; i < 4; i++) {
            int idx = threadIdx.x + i * 256;   // 0..1023
            int r = idx >> 4, col = idx & 15;
            int kg = kbase + kc * KCH + r;
            float4 kv = {0.f, 0.f, 0.f, 0.f}, vv = {0.f, 0.f, 0.f, 0.f};
            if (kg >= 0 && kg < SS) {
                size_t off = (size_t)(b * SS + kg) * DD + h * DHH;
                kv = ((const float4*)(k + off))[col];
                vv = ((const float4*)(v + off))[col];
            }
            ks[r][col] = kv;
            vs[r][col] = vv;
        }
        __syncthreads();

        int j0 = kc * KCH;
        for (int j = 0; j < KCH; j++) {
            int jj = j0 + j;
            int kg = kbase + jj;
            bool valid = (jj >= qi) && (jj <= qi + 2 * W1C) && (kg >= 0) && (kg < SS);

            float s0 = 0.f, s1 = 0.f, s2 = 0.f, s3 = 0.f;
            #pragma unroll
            for (int cc = 0; cc < 16; cc++) {
                float4 k4 = ks[j][cc];
                s0 += qr[4*cc+0] * k4.x;
                s1 += qr[4*cc+1] * k4.y;
                s2 += qr[4*cc+2] * k4.z;
                s3 += qr[4*cc+3] * k4.w;
            }
            float sc = (s0 + s1) + (s2 + s3);

            if (valid) {
                float p;
                if (sc > m) {
                    float corr = __expf(m - sc);
                    l *= corr;
                    #pragma unroll
                    for (int d = 0; d < 64; d++) acc[d] *= corr;
                    m = sc;
                    p = 1.0f;
                } else {
                    p = __expf(sc - m);
                }
                l += p;
                #pragma unroll
                for (int cc = 0; cc < 16; cc++) {
                    float4 v4 = vs[j][cc];
                    acc[4*cc+0] += p * v4.x;
                    acc[4*cc+1] += p * v4.y;
                    acc[4*cc+2] += p * v4.z;
                    acc[4*cc+3] += p * v4.w;
                }
            }
        }
        __syncthreads();
    }

    float inv = 1.0f / l;
    float4* op = (float4*)(ctx + (size_t)qrow * DD + h * DHH);
    #pragma unroll
    for (int i = 0; i < 16; i++) {
        float4 o;
        o.x = acc[4*i+0] * inv; o.y = acc[4*i+1] * inv;
        o.z = acc[4*i+2] * inv; o.w = acc[4*i+3] * inv;
        op[i] = o;
    }
}

// ---------------- launch ----------------
extern "C" void kernel_launch(void* const* d_in, const int* in_sizes, int n_in,
                              void* d_out, int out_size)
{
    const int*   ids    = (const int*)  d_in[0];
    const float* state  = (const float*)d_in[1];
    const float* wemb   = (const float*)d_in[2];
    const float* pemb   = (const float*)d_in[3];
    const float* ln_e_g = (const float*)d_in[4];
    const float* ln_e_b = (const float*)d_in[5];
    const float* Wq     = (const float*)d_in[6];
    const float* bq     = (const float*)d_in[7];
    const float* Wk     = (const float*)d_in[8];
    const float* bk     = (const float*)d_in[9];
    const float* Wv     = (const float*)d_in[10];
    const float* bv     = (const float*)d_in[11];
    const float* Wo     = (const float*)d_in[12];
    const float* bo     = (const float*)d_in[13];
    const float* ln_a_g = (const float*)d_in[14];
    const float* ln_a_b = (const float*)d_in[15];
    float* out = (float*)d_out;

    float *x, *q, *k, *v, *ctx, *hx;
    cudaGetSymbolAddress((void**)&x,   g_x);
    cudaGetSymbolAddress((void**)&q,   g_q);
    cudaGetSymbolAddress((void**)&k,   g_k);
    cudaGetSymbolAddress((void**)&v,   g_v);
    cudaGetSymbolAddress((void**)&ctx, g_ctx);
    cudaGetSymbolAddress((void**)&hx,  g_h);

    embed_ln_kernel<<<MTOK, 256>>>(ids, wemb, pemb, ln_e_g, ln_e_b, x);

    dim3 ggrid(DD / BN, MTOK / BM);
    gemm_kernel<false><<<ggrid, 256>>>(x, Wq, bq, nullptr, q);
    gemm_kernel<false><<<ggrid, 256>>>(x, Wk, bk, nullptr, k);
    gemm_kernel<false><<<ggrid, 256>>>(x, Wv, bv, nullptr, v);

    attn_kernel<<<dim3(NCC, HH, BB), 256>>>(q, k, v, ctx);

    gemm_kernel<true><<<ggrid, 256>>>(ctx, Wo, bo, x, hx);

    ln_kernel<<<MTOK, 256>>>(hx, ln_a_g, ln_a_b, out);

    long long tail = (long long)out_size - (long long)MTOK * DD;
    if (tail > 0) {
        cudaMemcpyAsync(out + (size_t)MTOK * DD, state,
                        (size_t)tail * sizeof(float),
                        cudaMemcpyDeviceToDevice);
    }
}

// round 2
// speedup vs baseline: 1.6101x; 1.6101x over previous
#include <cuda_runtime.h>
#include <math.h>
#include <stdint.h>

#define BB 2
#define SS 4096
#define DD 768
#define HH 12
#define DHH 64
#define W1C 256
#define NCC 16
#define MTOK (BB*SS)   // 8192

// ---------------- scratch (device globals; no allocation allowed) ----------------
__device__ float g_x  [MTOK*DD];
__device__ float g_q  [MTOK*DD];
__device__ float g_k  [MTOK*DD];
__device__ float g_v  [MTOK*DD];
__device__ float g_ctx[MTOK*DD];
__device__ float g_h  [MTOK*DD];

// ---------------- block reduction: sum + sumsq over 256 threads ----------------
__device__ __forceinline__ void block_reduce2(float& s, float& s2) {
    __shared__ float r1[8], r2[8];
    const unsigned mask = 0xffffffffu;
    #pragma unroll
    for (int o = 16; o > 0; o >>= 1) {
        s  += __shfl_xor_sync(mask, s,  o);
        s2 += __shfl_xor_sync(mask, s2, o);
    }
    int w = threadIdx.x >> 5, lane = threadIdx.x & 31;
    if (lane == 0) { r1[w] = s; r2[w] = s2; }
    __syncthreads();
    float a = 0.f, b = 0.f;
    #pragma unroll
    for (int i = 0; i < 8; i++) { a += r1[i]; b += r2[i]; }
    s = a; s2 = b;
}

// ---------------- embedding gather + layernorm ----------------
__global__ __launch_bounds__(256) void embed_ln_kernel(
    const int* __restrict__ ids, const float* __restrict__ wemb,
    const float* __restrict__ pemb, const float* __restrict__ g,
    const float* __restrict__ b, float* __restrict__ x)
{
    int tok = blockIdx.x;
    int s_pos = tok & (SS - 1);
    int id = ids[tok];
    const float* we = wemb + (size_t)id * DD;
    const float* pe = pemb + (size_t)s_pos * DD;
    float v[3]; float sum = 0.f, sum2 = 0.f;
    #pragma unroll
    for (int i = 0; i < 3; i++) {
        int d = threadIdx.x + i * 256;
        v[i] = we[d] + pe[d];
        sum += v[i]; sum2 += v[i] * v[i];
    }
    block_reduce2(sum, sum2);
    float mean = sum * (1.0f / DD);
    float var  = sum2 * (1.0f / DD) - mean * mean;
    float rstd = rsqrtf(var + 1e-5f);
    float* row = x + (size_t)tok * DD;
    #pragma unroll
    for (int i = 0; i < 3; i++) {
        int d = threadIdx.x + i * 256;
        row[d] = (v[i] - mean) * rstd * g[d] + b[d];
    }
}

// ---------------- final layernorm ----------------
__global__ __launch_bounds__(256) void ln_kernel(
    const float* __restrict__ in, const float* __restrict__ g,
    const float* __restrict__ b, float* __restrict__ out)
{
    int tok = blockIdx.x;
    const float* row = in + (size_t)tok * DD;
    float v[3]; float sum = 0.f, sum2 = 0.f;
    #pragma unroll
    for (int i = 0; i < 3; i++) {
        int d = threadIdx.x + i * 256;
        v[i] = row[d];
        sum += v[i]; sum2 += v[i] * v[i];
    }
    block_reduce2(sum, sum2);
    float mean = sum * (1.0f / DD);
    float var  = sum2 * (1.0f / DD) - mean * mean;
    float rstd = rsqrtf(var + 1e-5f);
    float* orow = out + (size_t)tok * DD;
    #pragma unroll
    for (int i = 0; i < 3; i++) {
        int d = threadIdx.x + i * 256;
        orow[d] = (v[i] - mean) * rstd * g[d] + b[d];
    }
}

// ---------------- tf32 tensor-core GEMM ----------------
// C[M,768] = A[M,768] @ W[768,768] + bias (+res)
// Block tile 128x64, BK=16, 8 warps each computing a 32x32 warp tile via
// mma.sync.m16n8k8.tf32 (2 m-tiles x 4 n-tiles). cp.async double buffering.
#define GBM 128
#define GBN 64
#define GBK 16
#define GNIT (DD / GBK)   // 48
#define APAD 20           // bank = (4m + k) % 32 -> conflict-free fragment LDS
#define BPAD 72           // bank = (8k + n) % 32 -> conflict-free fragment LDS

__device__ __forceinline__ void cp16(uint32_t smem, const void* gmem) {
    asm volatile("cp.async.cg.shared.global [%0], [%1], 16;\n" :: "r"(smem), "l"(gmem));
}
__device__ __forceinline__ void cp_commit() { asm volatile("cp.async.commit_group;\n"); }
template<int N>
__device__ __forceinline__ void cp_wait() { asm volatile("cp.async.wait_group %0;\n" :: "n"(N)); }

template<bool RES>
__global__ __launch_bounds__(256) void gemm_tf32_kernel(
    const float* __restrict__ A, const float* __restrict__ W,
    const float* __restrict__ bias, const float* __restrict__ res,
    float* __restrict__ C)
{
    __shared__ float As[2][GBM][APAD];
    __shared__ float Bs[2][GBK][BPAD];

    const int tid = threadIdx.x;
    const int lane = tid & 31;
    const int wid = tid >> 5;
    const int wm = (wid & 3) * 32;   // warp row offset within block tile
    const int wn = (wid >> 2) * 32;  // warp col offset within block tile
    const int rowBase = blockIdx.y * GBM;
    const int colBase = blockIdx.x * GBN;

    // cp.async source/dest indexing
    const int a_row = tid >> 1;                  // 0..127
    const int a_col = (tid & 1) * 8;             // two float4 per row half? -> 8 floats
    const int b_row = tid >> 4;                  // 0..15
    const int b_col = (tid & 15) * 4;            // 0..60

    auto load_stage = [&](int st, int k0) {
        // A: 128x16 floats = 512 float4; thread loads 2 (16B each)
        const float* ga = A + (size_t)(rowBase + a_row) * DD + k0 + a_col;
        uint32_t sa = (uint32_t)__cvta_generic_to_shared(&As[st][a_row][a_col]);
        cp16(sa, ga);
        cp16(sa + 16, ga + 4);
        // B: 16x64 floats = 256 float4; thread loads 1
        const float* gb = W + (size_t)(k0 + b_row) * DD + colBase + b_col;
        uint32_t sb = (uint32_t)__cvta_generic_to_shared(&Bs[st][b_row][b_col]);
        cp16(sb, gb);
    };

    float acc[2][4][4];
    #pragma unroll
    for (int i = 0; i < 2; i++)
        #pragma unroll
        for (int j = 0; j < 4; j++)
            #pragma unroll
            for (int r = 0; r < 4; r++) acc[i][j][r] = 0.f;

    load_stage(0, 0);
    cp_commit();

    for (int it = 0; it < GNIT; it++) {
        if (it + 1 < GNIT) {
            load_stage((it + 1) & 1, (it + 1) * GBK);
            cp_commit();
            cp_wait<1>();
        } else {
            cp_wait<0>();
        }
        __syncthreads();

        int st = it & 1;
        #pragma unroll
        for (int ks = 0; ks < 2; ks++) {
            int kb = ks * 8;
            uint32_t a[2][4];
            #pragma unroll
            for (int mi = 0; mi < 2; mi++) {
                int r = wm + mi * 16 + (lane >> 2);
                int c = kb + (lane & 3);
                a[mi][0] = __float_as_uint(As[st][r    ][c    ]);
                a[mi][1] = __float_as_uint(As[st][r + 8][c    ]);
                a[mi][2] = __float_as_uint(As[st][r    ][c + 4]);
                a[mi][3] = __float_as_uint(As[st][r + 8][c + 4]);
            }
            uint32_t b[4][2];
            #pragma unroll
            for (int ni = 0; ni < 4; ni++) {
                int kk = kb + (lane & 3);
                int n = wn + ni * 8 + (lane >> 2);
                b[ni][0] = __float_as_uint(Bs[st][kk    ][n]);
                b[ni][1] = __float_as_uint(Bs[st][kk + 4][n]);
            }
            #pragma unroll
            for (int mi = 0; mi < 2; mi++)
                #pragma unroll
                for (int ni = 0; ni < 4; ni++) {
                    asm volatile(
                        "mma.sync.aligned.m16n8k8.row.col.f32.tf32.tf32.f32 "
                        "{%0,%1,%2,%3}, {%4,%5,%6,%7}, {%8,%9}, {%0,%1,%2,%3};\n"
                        : "+f"(acc[mi][ni][0]), "+f"(acc[mi][ni][1]),
                          "+f"(acc[mi][ni][2]), "+f"(acc[mi][ni][3])
                        : "r"(a[mi][0]), "r"(a[mi][1]), "r"(a[mi][2]), "r"(a[mi][3]),
                          "r"(b[ni][0]), "r"(b[ni][1]));
                }
        }
        __syncthreads();
    }

    // epilogue: bias (+residual), float2 stores
    #pragma unroll
    for (int mi = 0; mi < 2; mi++) {
        #pragma unroll
        for (int rr = 0; rr < 2; rr++) {
            int row = rowBase + wm + mi * 16 + (lane >> 2) + rr * 8;
            #pragma unroll
            for (int ni = 0; ni < 4; ni++) {
                int col = colBase + wn + ni * 8 + 2 * (lane & 3);
                float c0 = acc[mi][ni][2 * rr + 0] + bias[col];
                float c1 = acc[mi][ni][2 * rr + 1] + bias[col + 1];
                if (RES) {
                    const float2 r2 = *(const float2*)&res[(size_t)row * DD + col];
                    c0 += r2.x; c1 += r2.y;
                }
                float2 o = {c0, c1};
                *(float2*)&C[(size_t)row * DD + col] = o;
            }
        }
    }
}

// ---------------- banded attention ----------------
// grid (NC, H, B); 256 threads; thread t handles query row t of the chunk.
#define KCH 64   // keys per smem chunk

__global__ __launch_bounds__(256, 1) void attn_kernel(
    const float* __restrict__ q, const float* __restrict__ k,
    const float* __restrict__ v, float* __restrict__ ctx)
{
    __shared__ float4 ks[KCH][16];
    __shared__ float4 vs[KCH][16];

    int c = blockIdx.x, h = blockIdx.y, b = blockIdx.z;
    int qi = threadIdx.x;
    int qrow = b * SS + c * W1C + qi;
    const float scale = 0.125f;   // 64^-0.5

    float qr[64];
    {
        const float4* qp = (const float4*)(q + (size_t)qrow * DD + h * DHH);
        #pragma unroll
        for (int i = 0; i < 16; i++) {
            float4 t = qp[i];
            qr[4*i+0] = t.x * scale; qr[4*i+1] = t.y * scale;
            qr[4*i+2] = t.z * scale; qr[4*i+3] = t.w * scale;
        }
    }
    float acc[64];
    #pragma unroll
    for (int d = 0; d < 64; d++) acc[d] = 0.f;
    float m = -INFINITY, l = 0.f;

    int kbase = c * W1C - W1C;   // global key row for j=0

    for (int kc = 0; kc < (3 * W1C) / KCH; kc++) {
        #pragma unroll
        for (int i = 0; i < 4; i++) {
            int idx = threadIdx.x + i * 256;   // 0..1023
            int r = idx >> 4, col = idx & 15;
            int kg = kbase + kc * KCH + r;
            float4 kv = {0.f, 0.f, 0.f, 0.f}, vv = {0.f, 0.f, 0.f, 0.f};
            if (kg >= 0 && kg < SS) {
                size_t off = (size_t)(b * SS + kg) * DD + h * DHH;
                kv = ((const float4*)(k + off))[col];
                vv = ((const float4*)(v + off))[col];
            }
            ks[r][col] = kv;
            vs[r][col] = vv;
        }
        __syncthreads();

        int j0 = kc * KCH;
        for (int j = 0; j < KCH; j++) {
            int jj = j0 + j;
            int kg = kbase + jj;
            bool valid = (jj >= qi) && (jj <= qi + 2 * W1C) && (kg >= 0) && (kg < SS);

            if (valid) {
                float s0 = 0.f, s1 = 0.f, s2 = 0.f, s3 = 0.f;
                #pragma unroll
                for (int cc = 0; cc < 16; cc++) {
                    float4 k4 = ks[j][cc];
                    s0 += qr[4*cc+0] * k4.x;
                    s1 += qr[4*cc+1] * k4.y;
                    s2 += qr[4*cc+2] * k4.z;
                    s3 += qr[4*cc+3] * k4.w;
                }
                float sc = (s0 + s1) + (s2 + s3);

                float p;
                if (sc > m) {
                    float corr = __expf(m - sc);
                    l *= corr;
                    #pragma unroll
                    for (int d = 0; d < 64; d++) acc[d] *= corr;
                    m = sc;
                    p = 1.0f;
                } else {
                    p = __expf(sc - m);
                }
                l += p;
                #pragma unroll
                for (int cc = 0; cc < 16; cc++) {
                    float4 v4 = vs[j][cc];
                    acc[4*cc+0] += p * v4.x;
                    acc[4*cc+1] += p * v4.y;
                    acc[4*cc+2] += p * v4.z;
                    acc[4*cc+3] += p * v4.w;
                }
            }
        }
        __syncthreads();
    }

    float inv = 1.0f / l;
    float4* op = (float4*)(ctx + (size_t)qrow * DD + h * DHH);
    #pragma unroll
    for (int i = 0; i < 16; i++) {
        float4 o;
        o.x = acc[4*i+0] * inv; o.y = acc[4*i+1] * inv;
        o.z = acc[4*i+2] * inv; o.w = acc[4*i+3] * inv;
        op[i] = o;
    }
}

// ---------------- launch ----------------
extern "C" void kernel_launch(void* const* d_in, const int* in_sizes, int n_in,
                              void* d_out, int out_size)
{
    const int*   ids    = (const int*)  d_in[0];
    const float* state  = (const float*)d_in[1];
    const float* wemb   = (const float*)d_in[2];
    const float* pemb   = (const float*)d_in[3];
    const float* ln_e_g = (const float*)d_in[4];
    const float* ln_e_b = (const float*)d_in[5];
    const float* Wq     = (const float*)d_in[6];
    const float* bq     = (const float*)d_in[7];
    const float* Wk     = (const float*)d_in[8];
    const float* bk     = (const float*)d_in[9];
    const float* Wv     = (const float*)d_in[10];
    const float* bv     = (const float*)d_in[11];
    const float* Wo     = (const float*)d_in[12];
    const float* bo     = (const float*)d_in[13];
    const float* ln_a_g = (const float*)d_in[14];
    const float* ln_a_b = (const float*)d_in[15];
    float* out = (float*)d_out;

    float *x, *q, *k, *v, *ctx, *hx;
    cudaGetSymbolAddress((void**)&x,   g_x);
    cudaGetSymbolAddress((void**)&q,   g_q);
    cudaGetSymbolAddress((void**)&k,   g_k);
    cudaGetSymbolAddress((void**)&v,   g_v);
    cudaGetSymbolAddress((void**)&ctx, g_ctx);
    cudaGetSymbolAddress((void**)&hx,  g_h);

    embed_ln_kernel<<<MTOK, 256>>>(ids, wemb, pemb, ln_e_g, ln_e_b, x);

    dim3 ggrid(DD / GBN, MTOK / GBM);   // (12, 64)
    gemm_tf32_kernel<false><<<ggrid, 256>>>(x, Wq, bq, nullptr, q);
    gemm_tf32_kernel<false><<<ggrid, 256>>>(x, Wk, bk, nullptr, k);
    gemm_tf32_kernel<false><<<ggrid, 256>>>(x, Wv, bv, nullptr, v);

    attn_kernel<<<dim3(NCC, HH, BB), 256>>>(q, k, v, ctx);

    gemm_tf32_kernel<true><<<ggrid, 256>>>(ctx, Wo, bo, x, hx);

    ln_kernel<<<MTOK, 256>>>(hx, ln_a_g, ln_a_b, out);

    long long tail = (long long)out_size - (long long)MTOK * DD;
    if (tail > 0) {
        cudaMemcpyAsync(out + (size_t)MTOK * DD, state,
                        (size_t)tail * sizeof(float),
                        cudaMemcpyDeviceToDevice);
    }
}

// round 3
// speedup vs baseline: 3.2363x; 2.0100x over previous
#include <cuda_runtime.h>
#include <math.h>
#include <stdint.h>

#define BB 2
#define SS 4096
#define DD 768
#define HH 12
#define DHH 64
#define W1C 256
#define NCC 16
#define MTOK (BB*SS)   // 8192

// ---------------- scratch (device globals; no allocation allowed) ----------------
__device__ float g_x  [MTOK*DD];
__device__ float g_q  [MTOK*DD];
__device__ float g_k  [MTOK*DD];
__device__ float g_v  [MTOK*DD];
__device__ float g_ctx[MTOK*DD];
__device__ float g_h  [MTOK*DD];

// ---------------- block reduction: sum + sumsq over 256 threads ----------------
__device__ __forceinline__ void block_reduce2(float& s, float& s2) {
    __shared__ float r1[8], r2[8];
    const unsigned mask = 0xffffffffu;
    #pragma unroll
    for (int o = 16; o > 0; o >>= 1) {
        s  += __shfl_xor_sync(mask, s,  o);
        s2 += __shfl_xor_sync(mask, s2, o);
    }
    int w = threadIdx.x >> 5, lane = threadIdx.x & 31;
    if (lane == 0) { r1[w] = s; r2[w] = s2; }
    __syncthreads();
    float a = 0.f, b = 0.f;
    #pragma unroll
    for (int i = 0; i < 8; i++) { a += r1[i]; b += r2[i]; }
    s = a; s2 = b;
}

// ---------------- embedding gather + layernorm ----------------
__global__ __launch_bounds__(256) void embed_ln_kernel(
    const int* __restrict__ ids, const float* __restrict__ wemb,
    const float* __restrict__ pemb, const float* __restrict__ g,
    const float* __restrict__ b, float* __restrict__ x)
{
    int tok = blockIdx.x;
    int s_pos = tok & (SS - 1);
    int id = ids[tok];
    const float* we = wemb + (size_t)id * DD;
    const float* pe = pemb + (size_t)s_pos * DD;
    float v[3]; float sum = 0.f, sum2 = 0.f;
    #pragma unroll
    for (int i = 0; i < 3; i++) {
        int d = threadIdx.x + i * 256;
        v[i] = we[d] + pe[d];
        sum += v[i]; sum2 += v[i] * v[i];
    }
    block_reduce2(sum, sum2);
    float mean = sum * (1.0f / DD);
    float var  = sum2 * (1.0f / DD) - mean * mean;
    float rstd = rsqrtf(var + 1e-5f);
    float* row = x + (size_t)tok * DD;
    #pragma unroll
    for (int i = 0; i < 3; i++) {
        int d = threadIdx.x + i * 256;
        row[d] = (v[i] - mean) * rstd * g[d] + b[d];
    }
}

// ---------------- final layernorm ----------------
__global__ __launch_bounds__(256) void ln_kernel(
    const float* __restrict__ in, const float* __restrict__ g,
    const float* __restrict__ b, float* __restrict__ out)
{
    int tok = blockIdx.x;
    const float* row = in + (size_t)tok * DD;
    float v[3]; float sum = 0.f, sum2 = 0.f;
    #pragma unroll
    for (int i = 0; i < 3; i++) {
        int d = threadIdx.x + i * 256;
        v[i] = row[d];
        sum += v[i]; sum2 += v[i] * v[i];
    }
    block_reduce2(sum, sum2);
    float mean = sum * (1.0f / DD);
    float var  = sum2 * (1.0f / DD) - mean * mean;
    float rstd = rsqrtf(var + 1e-5f);
    float* orow = out + (size_t)tok * DD;
    #pragma unroll
    for (int i = 0; i < 3; i++) {
        int d = threadIdx.x + i * 256;
        orow[d] = (v[i] - mean) * rstd * g[d] + b[d];
    }
}

// ---------------- tf32 tensor-core GEMM ----------------
#define GBM 128
#define GBN 64
#define GBK 16
#define GNIT (DD / GBK)   // 48
#define APAD 20
#define BPAD 72

__device__ __forceinline__ void cp16(uint32_t smem, const void* gmem) {
    asm volatile("cp.async.cg.shared.global [%0], [%1], 16;\n" :: "r"(smem), "l"(gmem));
}
__device__ __forceinline__ void cp_commit() { asm volatile("cp.async.commit_group;\n"); }
template<int N>
__device__ __forceinline__ void cp_wait() { asm volatile("cp.async.wait_group %0;\n" :: "n"(N)); }

__device__ __forceinline__ void mma_tf32(float* c, const uint32_t* a, const uint32_t* b) {
    asm volatile(
        "mma.sync.aligned.m16n8k8.row.col.f32.tf32.tf32.f32 "
        "{%0,%1,%2,%3}, {%4,%5,%6,%7}, {%8,%9}, {%0,%1,%2,%3};\n"
        : "+f"(c[0]), "+f"(c[1]), "+f"(c[2]), "+f"(c[3])
        : "r"(a[0]), "r"(a[1]), "r"(a[2]), "r"(a[3]), "r"(b[0]), "r"(b[1]));
}

template<bool RES>
__global__ __launch_bounds__(256) void gemm_tf32_kernel(
    const float* __restrict__ A, const float* __restrict__ W,
    const float* __restrict__ bias, const float* __restrict__ res,
    float* __restrict__ C)
{
    __shared__ float As[2][GBM][APAD];
    __shared__ float Bs[2][GBK][BPAD];

    const int tid = threadIdx.x;
    const int lane = tid & 31;
    const int wid = tid >> 5;
    const int wm = (wid & 3) * 32;
    const int wn = (wid >> 2) * 32;
    const int rowBase = blockIdx.y * GBM;
    const int colBase = blockIdx.x * GBN;

    const int a_row = tid >> 1;
    const int a_col = (tid & 1) * 8;
    const int b_row = tid >> 4;
    const int b_col = (tid & 15) * 4;

    auto load_stage = [&](int st, int k0) {
        const float* ga = A + (size_t)(rowBase + a_row) * DD + k0 + a_col;
        uint32_t sa = (uint32_t)__cvta_generic_to_shared(&As[st][a_row][a_col]);
        cp16(sa, ga);
        cp16(sa + 16, ga + 4);
        const float* gb = W + (size_t)(k0 + b_row) * DD + colBase + b_col;
        uint32_t sb = (uint32_t)__cvta_generic_to_shared(&Bs[st][b_row][b_col]);
        cp16(sb, gb);
    };

    float acc[2][4][4];
    #pragma unroll
    for (int i = 0; i < 2; i++)
        #pragma unroll
        for (int j = 0; j < 4; j++)
            #pragma unroll
            for (int r = 0; r < 4; r++) acc[i][j][r] = 0.f;

    load_stage(0, 0);
    cp_commit();

    for (int it = 0; it < GNIT; it++) {
        if (it + 1 < GNIT) {
            load_stage((it + 1) & 1, (it + 1) * GBK);
            cp_commit();
            cp_wait<1>();
        } else {
            cp_wait<0>();
        }
        __syncthreads();

        int st = it & 1;
        #pragma unroll
        for (int ks = 0; ks < 2; ks++) {
            int kb = ks * 8;
            uint32_t a[2][4];
            #pragma unroll
            for (int mi = 0; mi < 2; mi++) {
                int r = wm + mi * 16 + (lane >> 2);
                int c = kb + (lane & 3);
                a[mi][0] = __float_as_uint(As[st][r    ][c    ]);
                a[mi][1] = __float_as_uint(As[st][r + 8][c    ]);
                a[mi][2] = __float_as_uint(As[st][r    ][c + 4]);
                a[mi][3] = __float_as_uint(As[st][r + 8][c + 4]);
            }
            uint32_t b[4][2];
            #pragma unroll
            for (int ni = 0; ni < 4; ni++) {
                int kk = kb + (lane & 3);
                int n = wn + ni * 8 + (lane >> 2);
                b[ni][0] = __float_as_uint(Bs[st][kk    ][n]);
                b[ni][1] = __float_as_uint(Bs[st][kk + 4][n]);
            }
            #pragma unroll
            for (int mi = 0; mi < 2; mi++)
                #pragma unroll
                for (int ni = 0; ni < 4; ni++)
                    mma_tf32(acc[mi][ni], a[mi], b[ni]);
        }
        __syncthreads();
    }

    #pragma unroll
    for (int mi = 0; mi < 2; mi++) {
        #pragma unroll
        for (int rr = 0; rr < 2; rr++) {
            int row = rowBase + wm + mi * 16 + (lane >> 2) + rr * 8;
            #pragma unroll
            for (int ni = 0; ni < 4; ni++) {
                int col = colBase + wn + ni * 8 + 2 * (lane & 3);
                float c0 = acc[mi][ni][2 * rr + 0] + bias[col];
                float c1 = acc[mi][ni][2 * rr + 1] + bias[col + 1];
                if (RES) {
                    const float2 r2 = *(const float2*)&res[(size_t)row * DD + col];
                    c0 += r2.x; c1 += r2.y;
                }
                float2 o = {c0, c1};
                *(float2*)&C[(size_t)row * DD + col] = o;
            }
        }
    }
}

// ---------------- banded attention, tensor-core flash style ----------------
// grid (NCC*4, HH, BB), 128 threads (4 warps). Block handles 64 query rows of
// one (b,h) chunk sub-tile. Key band = 9 aligned 64-key tiles, streamed via smem.
// P tile aliases the K smem buffer (K dead after QK mma).
#define AT_PAD 68   // (pad%32)==4 -> fragment LDS bank = 4*row+col pattern, conflict-free

__global__ __launch_bounds__(128) void attn_mma_kernel(
    const float* __restrict__ q, const float* __restrict__ k,
    const float* __restrict__ v, float* __restrict__ ctx)
{
    __shared__ float Ks[64][AT_PAD];   // K tile; reused as P tile; also transient Q
    __shared__ float Vs[64][AT_PAD];

    const int tid = threadIdx.x;
    const int lane = tid & 31;
    const int wid = tid >> 5;
    const int g = lane >> 2;      // 0..7
    const int t = lane & 3;       // 0..3
    const int wr = wid * 16;      // warp's first query row within tile

    const int sub = blockIdx.x & 3;
    const int c   = blockIdx.x >> 2;
    const int h   = blockIdx.y;
    const int b   = blockIdx.z;
    const int q0  = c * W1C + sub * 64;           // global seq index of query row 0
    const size_t bh_off = (size_t)b * SS * DD + h * DHH;
    const float scale = 0.125f;

    // ---- load Q tile (64x64) into Ks, then into register A-fragments ----
    for (int i = tid; i < 64 * 16; i += 128) {
        int r = i >> 4, c4 = i & 15;
        float4 t4 = *(const float4*)(q + bh_off + (size_t)(q0 + r) * DD + c4 * 4);
        *(float4*)&Ks[r][c4 * 4] = t4;
    }
    __syncthreads();

    uint32_t qa[8][4];
    #pragma unroll
    for (int kb = 0; kb < 8; kb++) {
        qa[kb][0] = __float_as_uint(Ks[wr + g    ][kb * 8 + t    ] * scale);
        qa[kb][1] = __float_as_uint(Ks[wr + 8 + g][kb * 8 + t    ] * scale);
        qa[kb][2] = __float_as_uint(Ks[wr + g    ][kb * 8 + t + 4] * scale);
        qa[kb][3] = __float_as_uint(Ks[wr + 8 + g][kb * 8 + t + 4] * scale);
    }
    __syncthreads();

    float o[8][4];
    #pragma unroll
    for (int ni = 0; ni < 8; ni++)
        #pragma unroll
        for (int r = 0; r < 4; r++) o[ni][r] = 0.f;
    float m0 = -1e30f, m1 = -1e30f, l0 = 0.f, l1 = 0.f;

    const int qg0 = q0 + wr + g;   // this thread's row pair (global)
    const int qg1 = qg0 + 8;
    const int kstart = q0 - W1C;

    for (int j = 0; j < 9; j++) {
        int kt0 = kstart + j * 64;
        if (kt0 < 0 || kt0 >= SS) continue;   // tiles are 64-aligned: never partial

        // ---- load K/V tile (64x64 each), coalesced ----
        for (int i = tid; i < 64 * 16; i += 128) {
            int r = i >> 4, c4 = i & 15;
            size_t off = bh_off + (size_t)(kt0 + r) * DD + c4 * 4;
            *(float4*)&Ks[r][c4 * 4] = *(const float4*)(k + off);
            *(float4*)&Vs[r][c4 * 4] = *(const float4*)(v + off);
        }
        __syncthreads();

        // ---- S = Q @ K^T (8 n-frags over 64 keys) ----
        float s[8][4];
        #pragma unroll
        for (int ni = 0; ni < 8; ni++) {
            s[ni][0] = s[ni][1] = s[ni][2] = s[ni][3] = 0.f;
            #pragma unroll
            for (int kb = 0; kb < 8; kb++) {
                uint32_t bb[2];
                bb[0] = __float_as_uint(Ks[ni * 8 + g][kb * 8 + t    ]);
                bb[1] = __float_as_uint(Ks[ni * 8 + g][kb * 8 + t + 4]);
                mma_tf32(s[ni], qa[kb], bb);
            }
        }
        __syncthreads();   // all warps done reading Ks; Ps (alias) writes follow

        // ---- band mask (only boundary tiles need it) ----
        if (j == 0 || j == 8) {
            #pragma unroll
            for (int ni = 0; ni < 8; ni++) {
                int kg = kt0 + ni * 8 + 2 * t;
                if (kg < qg0 - W1C || kg > qg0 + W1C) s[ni][0] = -1e30f;
                if (kg + 1 < qg0 - W1C || kg + 1 > qg0 + W1C) s[ni][1] = -1e30f;
                if (kg < qg1 - W1C || kg > qg1 + W1C) s[ni][2] = -1e30f;
                if (kg + 1 < qg1 - W1C || kg + 1 > qg1 + W1C) s[ni][3] = -1e30f;
            }
        }

        // ---- online softmax, rescale O, write P (alias Ks) ----
        {
            float mx0 = -1e30f, mx1 = -1e30f;
            #pragma unroll
            for (int ni = 0; ni < 8; ni++) {
                mx0 = fmaxf(mx0, fmaxf(s[ni][0], s[ni][1]));
                mx1 = fmaxf(mx1, fmaxf(s[ni][2], s[ni][3]));
            }
            mx0 = fmaxf(mx0, __shfl_xor_sync(0xffffffffu, mx0, 1));
            mx0 = fmaxf(mx0, __shfl_xor_sync(0xffffffffu, mx0, 2));
            mx1 = fmaxf(mx1, __shfl_xor_sync(0xffffffffu, mx1, 1));
            mx1 = fmaxf(mx1, __shfl_xor_sync(0xffffffffu, mx1, 2));
            float nm0 = fmaxf(m0, mx0), nm1 = fmaxf(m1, mx1);
            float cor0 = __expf(m0 - nm0), cor1 = __expf(m1 - nm1);
            float rs0 = 0.f, rs1 = 0.f;
            #pragma unroll
            for (int ni = 0; ni < 8; ni++) {
                float p00 = __expf(s[ni][0] - nm0);
                float p01 = __expf(s[ni][1] - nm0);
                float p10 = __expf(s[ni][2] - nm1);
                float p11 = __expf(s[ni][3] - nm1);
                rs0 += p00 + p01; rs1 += p10 + p11;
                float2 w0 = {p00, p01}, w1 = {p10, p11};
                *(float2*)&Ks[wr + g    ][ni * 8 + 2 * t] = w0;
                *(float2*)&Ks[wr + 8 + g][ni * 8 + 2 * t] = w1;
                o[ni][0] *= cor0; o[ni][1] *= cor0;
                o[ni][2] *= cor1; o[ni][3] *= cor1;
            }
            rs0 += __shfl_xor_sync(0xffffffffu, rs0, 1);
            rs0 += __shfl_xor_sync(0xffffffffu, rs0, 2);
            rs1 += __shfl_xor_sync(0xffffffffu, rs1, 1);
            rs1 += __shfl_xor_sync(0xffffffffu, rs1, 2);
            l0 = l0 * cor0 + rs0; l1 = l1 * cor1 + rs1;
            m0 = nm0; m1 = nm1;
        }
        __syncwarp();   // P rows are warp-private; make writes visible in-warp

        // ---- O += P @ V ----
        #pragma unroll
        for (int kb = 0; kb < 8; kb++) {
            uint32_t a[4];
            a[0] = __float_as_uint(Ks[wr + g    ][kb * 8 + t    ]);
            a[1] = __float_as_uint(Ks[wr + 8 + g][kb * 8 + t    ]);
            a[2] = __float_as_uint(Ks[wr + g    ][kb * 8 + t + 4]);
            a[3] = __float_as_uint(Ks[wr + 8 + g][kb * 8 + t + 4]);
            #pragma unroll
            for (int ni = 0; ni < 8; ni++) {
                uint32_t bb[2];
                bb[0] = __float_as_uint(Vs[kb * 8 + t    ][ni * 8 + g]);
                bb[1] = __float_as_uint(Vs[kb * 8 + t + 4][ni * 8 + g]);
                mma_tf32(o[ni], a, bb);
            }
        }
        __syncthreads();   // done with Ks/Vs before next tile's loads
    }

    // ---- epilogue: normalize and store ----
    float inv0 = 1.0f / l0, inv1 = 1.0f / l1;
    #pragma unroll
    for (int ni = 0; ni < 8; ni++) {
        int col = ni * 8 + 2 * t;
        float2 w0 = {o[ni][0] * inv0, o[ni][1] * inv0};
        float2 w1 = {o[ni][2] * inv1, o[ni][3] * inv1};
        *(float2*)(ctx + bh_off + (size_t)qg0 * DD + col) = w0;
        *(float2*)(ctx + bh_off + (size_t)qg1 * DD + col) = w1;
    }
}

// ---------------- launch ----------------
extern "C" void kernel_launch(void* const* d_in, const int* in_sizes, int n_in,
                              void* d_out, int out_size)
{
    const int*   ids    = (const int*)  d_in[0];
    const float* state  = (const float*)d_in[1];
    const float* wemb   = (const float*)d_in[2];
    const float* pemb   = (const float*)d_in[3];
    const float* ln_e_g = (const float*)d_in[4];
    const float* ln_e_b = (const float*)d_in[5];
    const float* Wq     = (const float*)d_in[6];
    const float* bq     = (const float*)d_in[7];
    const float* Wk     = (const float*)d_in[8];
    const float* bk     = (const float*)d_in[9];
    const float* Wv     = (const float*)d_in[10];
    const float* bv     = (const float*)d_in[11];
    const float* Wo     = (const float*)d_in[12];
    const float* bo     = (const float*)d_in[13];
    const float* ln_a_g = (const float*)d_in[14];
    const float* ln_a_b = (const float*)d_in[15];
    float* out = (float*)d_out;

    float *x, *q, *k, *v, *ctx, *hx;
    cudaGetSymbolAddress((void**)&x,   g_x);
    cudaGetSymbolAddress((void**)&q,   g_q);
    cudaGetSymbolAddress((void**)&k,   g_k);
    cudaGetSymbolAddress((void**)&v,   g_v);
    cudaGetSymbolAddress((void**)&ctx, g_ctx);
    cudaGetSymbolAddress((void**)&hx,  g_h);

    embed_ln_kernel<<<MTOK, 256>>>(ids, wemb, pemb, ln_e_g, ln_e_b, x);

    dim3 ggrid(DD / GBN, MTOK / GBM);   // (12, 64)
    gemm_tf32_kernel<false><<<ggrid, 256>>>(x, Wq, bq, nullptr, q);
    gemm_tf32_kernel<false><<<ggrid, 256>>>(x, Wk, bk, nullptr, k);
    gemm_tf32_kernel<false><<<ggrid, 256>>>(x, Wv, bv, nullptr, v);

    attn_mma_kernel<<<dim3(NCC * 4, HH, BB), 128>>>(q, k, v, ctx);

    gemm_tf32_kernel<true><<<ggrid, 256>>>(ctx, Wo, bo, x, hx);

    ln_kernel<<<MTOK, 256>>>(hx, ln_a_g, ln_a_b, out);

    long long tail = (long long)out_size - (long long)MTOK * DD;
    if (tail > 0) {
        cudaMemcpyAsync(out + (size_t)MTOK * DD, state,
                        (size_t)tail * sizeof(float),
                        cudaMemcpyDeviceToDevice);
    }
}

// round 4
// speedup vs baseline: 3.5972x; 1.1115x over previous
#include <cuda_runtime.h>
#include <math.h>
#include <stdint.h>

#define BB 2
#define SS 4096
#define DD 768
#define HH 12
#define DHH 64
#define W1C 256
#define NCC 16
#define MTOK (BB*SS)   // 8192

// ---------------- scratch (device globals; no allocation allowed) ----------------
__device__ float g_x  [MTOK*DD];
__device__ float g_q  [MTOK*DD];
__device__ float g_k  [MTOK*DD];
__device__ float g_v  [MTOK*DD];
__device__ float g_ctx[MTOK*DD];
__device__ float g_h  [MTOK*DD];

// ---------------- block reduction: sum + sumsq over 256 threads ----------------
__device__ __forceinline__ void block_reduce2(float& s, float& s2) {
    __shared__ float r1[8], r2[8];
    const unsigned mask = 0xffffffffu;
    #pragma unroll
    for (int o = 16; o > 0; o >>= 1) {
        s  += __shfl_xor_sync(mask, s,  o);
        s2 += __shfl_xor_sync(mask, s2, o);
    }
    int w = threadIdx.x >> 5, lane = threadIdx.x & 31;
    if (lane == 0) { r1[w] = s; r2[w] = s2; }
    __syncthreads();
    float a = 0.f, b = 0.f;
    #pragma unroll
    for (int i = 0; i < 8; i++) { a += r1[i]; b += r2[i]; }
    s = a; s2 = b;
}

// ---------------- embedding gather + layernorm ----------------
__global__ __launch_bounds__(256) void embed_ln_kernel(
    const int* __restrict__ ids, const float* __restrict__ wemb,
    const float* __restrict__ pemb, const float* __restrict__ g,
    const float* __restrict__ b, float* __restrict__ x)
{
    int tok = blockIdx.x;
    int s_pos = tok & (SS - 1);
    int id = ids[tok];
    const float* we = wemb + (size_t)id * DD;
    const float* pe = pemb + (size_t)s_pos * DD;
    float v[3]; float sum = 0.f, sum2 = 0.f;
    #pragma unroll
    for (int i = 0; i < 3; i++) {
        int d = threadIdx.x + i * 256;
        v[i] = we[d] + pe[d];
        sum += v[i]; sum2 += v[i] * v[i];
    }
    block_reduce2(sum, sum2);
    float mean = sum * (1.0f / DD);
    float var  = sum2 * (1.0f / DD) - mean * mean;
    float rstd = rsqrtf(var + 1e-5f);
    float* row = x + (size_t)tok * DD;
    #pragma unroll
    for (int i = 0; i < 3; i++) {
        int d = threadIdx.x + i * 256;
        row[d] = (v[i] - mean) * rstd * g[d] + b[d];
    }
}

// ---------------- final layernorm ----------------
__global__ __launch_bounds__(256) void ln_kernel(
    const float* __restrict__ in, const float* __restrict__ g,
    const float* __restrict__ b, float* __restrict__ out)
{
    int tok = blockIdx.x;
    const float* row = in + (size_t)tok * DD;
    float v[3]; float sum = 0.f, sum2 = 0.f;
    #pragma unroll
    for (int i = 0; i < 3; i++) {
        int d = threadIdx.x + i * 256;
        v[i] = row[d];
        sum += v[i]; sum2 += v[i] * v[i];
    }
    block_reduce2(sum, sum2);
    float mean = sum * (1.0f / DD);
    float var  = sum2 * (1.0f / DD) - mean * mean;
    float rstd = rsqrtf(var + 1e-5f);
    float* orow = out + (size_t)tok * DD;
    #pragma unroll
    for (int i = 0; i < 3; i++) {
        int d = threadIdx.x + i * 256;
        orow[d] = (v[i] - mean) * rstd * g[d] + b[d];
    }
}

// ---------------- async copy helpers ----------------
__device__ __forceinline__ void cp16(uint32_t smem, const void* gmem) {
    asm volatile("cp.async.cg.shared.global [%0], [%1], 16;\n" :: "r"(smem), "l"(gmem));
}
__device__ __forceinline__ void cp_commit() { asm volatile("cp.async.commit_group;\n"); }
template<int N>
__device__ __forceinline__ void cp_wait() { asm volatile("cp.async.wait_group %0;\n" :: "n"(N)); }

__device__ __forceinline__ void mma_tf32(float* c, const uint32_t* a, const uint32_t* b) {
    asm volatile(
        "mma.sync.aligned.m16n8k8.row.col.f32.tf32.tf32.f32 "
        "{%0,%1,%2,%3}, {%4,%5,%6,%7}, {%8,%9}, {%0,%1,%2,%3};\n"
        : "+f"(c[0]), "+f"(c[1]), "+f"(c[2]), "+f"(c[3])
        : "r"(a[0]), "r"(a[1]), "r"(a[2]), "r"(a[3]), "r"(b[0]), "r"(b[1]));
}

// ---------------- tf32 tensor-core GEMM, 128x128 tile, 3-stage pipeline ----------------
// C_z[M,768] = A[M,768] @ W_z[768,768] + bias_z (+res). blockIdx.z selects (W,bias,C).
#define GBM 128
#define GBN 128
#define GBK 16
#define GNIT (DD / GBK)   // 48
#define NSTG 3
#define APAD 20           // 20 % 32 -> bank(20g + t) hits all 32 banks
#define BPAD 136          // 136 % 32 == 8 -> bank(8k + n) conflict-free
#define A_ST (GBM * APAD) // floats per A stage (2560)
#define B_ST (GBK * BPAD) // floats per B stage (2176)
#define GSMEM ((NSTG * (A_ST + B_ST)) * 4)  // 56832 bytes

extern __shared__ float g_smem[];

template<bool RES>
__global__ __launch_bounds__(256) void gemm_tf32_kernel(
    const float* __restrict__ A,
    const float* __restrict__ W0, const float* __restrict__ W1, const float* __restrict__ W2,
    const float* __restrict__ bias0, const float* __restrict__ bias1, const float* __restrict__ bias2,
    const float* __restrict__ res,
    float* __restrict__ C0, float* __restrict__ C1, float* __restrict__ C2)
{
    const int z = blockIdx.z;
    const float* W    = (z == 0) ? W0 : (z == 1) ? W1 : W2;
    const float* bias = (z == 0) ? bias0 : (z == 1) ? bias1 : bias2;
    float*       C    = (z == 0) ? C0 : (z == 1) ? C1 : C2;

    float* As = g_smem;                 // [NSTG][GBM][APAD]
    float* Bs = g_smem + NSTG * A_ST;   // [NSTG][GBK][BPAD]

    const int tid = threadIdx.x;
    const int lane = tid & 31;
    const int wid = tid >> 5;
    const int g = lane >> 2;    // 0..7
    const int t = lane & 3;     // 0..3
    const int wm = (wid & 1) * 64;    // warp m offset (2 warps in m)
    const int wn = (wid >> 1) * 32;   // warp n offset (4 warps in n)
    const int rowBase = blockIdx.y * GBM;
    const int colBase = blockIdx.x * GBN;

    const int a_row = tid >> 1;          // 0..127
    const int a_col = (tid & 1) * 8;     // 0 or 8
    const int b_row = tid >> 4;          // 0..15
    const int b_col = (tid & 15) * 8;    // 0..120

    auto load_stage = [&](int st, int k0) {
        const float* ga = A + (size_t)(rowBase + a_row) * DD + k0 + a_col;
        uint32_t sa = (uint32_t)__cvta_generic_to_shared(&As[st * A_ST + a_row * APAD + a_col]);
        cp16(sa, ga);
        cp16(sa + 16, ga + 4);
        const float* gb = W + (size_t)(k0 + b_row) * DD + colBase + b_col;
        uint32_t sb = (uint32_t)__cvta_generic_to_shared(&Bs[st * B_ST + b_row * BPAD + b_col]);
        cp16(sb, gb);
        cp16(sb + 16, gb + 4);
    };

    float acc[4][4][4];
    #pragma unroll
    for (int i = 0; i < 4; i++)
        #pragma unroll
        for (int j = 0; j < 4; j++)
            #pragma unroll
            for (int r = 0; r < 4; r++) acc[i][j][r] = 0.f;

    load_stage(0, 0);
    cp_commit();
    load_stage(1, GBK);
    cp_commit();

    for (int it = 0; it < GNIT; it++) {
        if (it + 2 < GNIT) load_stage((it + 2) % NSTG, (it + 2) * GBK);
        cp_commit();           // (possibly empty) keeps group counting uniform
        cp_wait<2>();          // stage `it` resident
        __syncthreads();

        const float* Ast = As + (it % NSTG) * A_ST;
        const float* Bst = Bs + (it % NSTG) * B_ST;

        #pragma unroll
        for (int ks = 0; ks < 2; ks++) {
            int kb = ks * 8;
            uint32_t a[4][4];
            #pragma unroll
            for (int mi = 0; mi < 4; mi++) {
                int r = wm + mi * 16 + g;
                int c = kb + t;
                a[mi][0] = __float_as_uint(Ast[(r    ) * APAD + c    ]);
                a[mi][1] = __float_as_uint(Ast[(r + 8) * APAD + c    ]);
                a[mi][2] = __float_as_uint(Ast[(r    ) * APAD + c + 4]);
                a[mi][3] = __float_as_uint(Ast[(r + 8) * APAD + c + 4]);
            }
            uint32_t b[4][2];
            #pragma unroll
            for (int ni = 0; ni < 4; ni++) {
                int kk = kb + t;
                int n = wn + ni * 8 + g;
                b[ni][0] = __float_as_uint(Bst[(kk    ) * BPAD + n]);
                b[ni][1] = __float_as_uint(Bst[(kk + 4) * BPAD + n]);
            }
            #pragma unroll
            for (int mi = 0; mi < 4; mi++)
                #pragma unroll
                for (int ni = 0; ni < 4; ni++)
                    mma_tf32(acc[mi][ni], a[mi], b[ni]);
        }
        __syncthreads();
    }

    #pragma unroll
    for (int mi = 0; mi < 4; mi++) {
        #pragma unroll
        for (int rr = 0; rr < 2; rr++) {
            int row = rowBase + wm + mi * 16 + g + rr * 8;
            #pragma unroll
            for (int ni = 0; ni < 4; ni++) {
                int col = colBase + wn + ni * 8 + 2 * t;
                float c0 = acc[mi][ni][2 * rr + 0] + bias[col];
                float c1 = acc[mi][ni][2 * rr + 1] + bias[col + 1];
                if (RES) {
                    const float2 r2 = *(const float2*)&res[(size_t)row * DD + col];
                    c0 += r2.x; c1 += r2.y;
                }
                float2 o = {c0, c1};
                *(float2*)&C[(size_t)row * DD + col] = o;
            }
        }
    }
}

// ---------------- banded attention, tensor-core flash style ----------------
#define AT_PAD 68

__global__ __launch_bounds__(128) void attn_mma_kernel(
    const float* __restrict__ q, const float* __restrict__ k,
    const float* __restrict__ v, float* __restrict__ ctx)
{
    __shared__ float Ks[64][AT_PAD];   // K tile; reused as P tile; also transient Q
    __shared__ float Vs[64][AT_PAD];

    const int tid = threadIdx.x;
    const int lane = tid & 31;
    const int wid = tid >> 5;
    const int g = lane >> 2;
    const int t = lane & 3;
    const int wr = wid * 16;

    const int sub = blockIdx.x & 3;
    const int c   = blockIdx.x >> 2;
    const int h   = blockIdx.y;
    const int b   = blockIdx.z;
    const int q0  = c * W1C + sub * 64;
    const size_t bh_off = (size_t)b * SS * DD + h * DHH;
    const float scale = 0.125f;

    for (int i = tid; i < 64 * 16; i += 128) {
        int r = i >> 4, c4 = i & 15;
        float4 t4 = *(const float4*)(q + bh_off + (size_t)(q0 + r) * DD + c4 * 4);
        *(float4*)&Ks[r][c4 * 4] = t4;
    }
    __syncthreads();

    uint32_t qa[8][4];
    #pragma unroll
    for (int kb = 0; kb < 8; kb++) {
        qa[kb][0] = __float_as_uint(Ks[wr + g    ][kb * 8 + t    ] * scale);
        qa[kb][1] = __float_as_uint(Ks[wr + 8 + g][kb * 8 + t    ] * scale);
        qa[kb][2] = __float_as_uint(Ks[wr + g    ][kb * 8 + t + 4] * scale);
        qa[kb][3] = __float_as_uint(Ks[wr + 8 + g][kb * 8 + t + 4] * scale);
    }
    __syncthreads();

    float o[8][4];
    #pragma unroll
    for (int ni = 0; ni < 8; ni++)
        #pragma unroll
        for (int r = 0; r < 4; r++) o[ni][r] = 0.f;
    float m0 = -1e30f, m1 = -1e30f, l0 = 0.f, l1 = 0.f;

    const int qg0 = q0 + wr + g;
    const int qg1 = qg0 + 8;
    const int kstart = q0 - W1C;

    for (int j = 0; j < 9; j++) {
        int kt0 = kstart + j * 64;
        if (kt0 < 0 || kt0 >= SS) continue;

        for (int i = tid; i < 64 * 16; i += 128) {
            int r = i >> 4, c4 = i & 15;
            size_t off = bh_off + (size_t)(kt0 + r) * DD + c4 * 4;
            *(float4*)&Ks[r][c4 * 4] = *(const float4*)(k + off);
            *(float4*)&Vs[r][c4 * 4] = *(const float4*)(v + off);
        }
        __syncthreads();

        float s[8][4];
        #pragma unroll
        for (int ni = 0; ni < 8; ni++) {
            s[ni][0] = s[ni][1] = s[ni][2] = s[ni][3] = 0.f;
            #pragma unroll
            for (int kb = 0; kb < 8; kb++) {
                uint32_t bb[2];
                bb[0] = __float_as_uint(Ks[ni * 8 + g][kb * 8 + t    ]);
                bb[1] = __float_as_uint(Ks[ni * 8 + g][kb * 8 + t + 4]);
                mma_tf32(s[ni], qa[kb], bb);
            }
        }
        __syncthreads();

        if (j == 0 || j == 8) {
            #pragma unroll
            for (int ni = 0; ni < 8; ni++) {
                int kg = kt0 + ni * 8 + 2 * t;
                if (kg < qg0 - W1C || kg > qg0 + W1C) s[ni][0] = -1e30f;
                if (kg + 1 < qg0 - W1C || kg + 1 > qg0 + W1C) s[ni][1] = -1e30f;
                if (kg < qg1 - W1C || kg > qg1 + W1C) s[ni][2] = -1e30f;
                if (kg + 1 < qg1 - W1C || kg + 1 > qg1 + W1C) s[ni][3] = -1e30f;
            }
        }

        {
            float mx0 = -1e30f, mx1 = -1e30f;
            #pragma unroll
            for (int ni = 0; ni < 8; ni++) {
                mx0 = fmaxf(mx0, fmaxf(s[ni][0], s[ni][1]));
                mx1 = fmaxf(mx1, fmaxf(s[ni][2], s[ni][3]));
            }
            mx0 = fmaxf(mx0, __shfl_xor_sync(0xffffffffu, mx0, 1));
            mx0 = fmaxf(mx0, __shfl_xor_sync(0xffffffffu, mx0, 2));
            mx1 = fmaxf(mx1, __shfl_xor_sync(0xffffffffu, mx1, 1));
            mx1 = fmaxf(mx1, __shfl_xor_sync(0xffffffffu, mx1, 2));
            float nm0 = fmaxf(m0, mx0), nm1 = fmaxf(m1, mx1);
            float cor0 = __expf(m0 - nm0), cor1 = __expf(m1 - nm1);
            float rs0 = 0.f, rs1 = 0.f;
            #pragma unroll
            for (int ni = 0; ni < 8; ni++) {
                float p00 = __expf(s[ni][0] - nm0);
                float p01 = __expf(s[ni][1] - nm0);
                float p10 = __expf(s[ni][2] - nm1);
                float p11 = __expf(s[ni][3] - nm1);
                rs0 += p00 + p01; rs1 += p10 + p11;
                float2 w0 = {p00, p01}, w1 = {p10, p11};
                *(float2*)&Ks[wr + g    ][ni * 8 + 2 * t] = w0;
                *(float2*)&Ks[wr + 8 + g][ni * 8 + 2 * t] = w1;
                o[ni][0] *= cor0; o[ni][1] *= cor0;
                o[ni][2] *= cor1; o[ni][3] *= cor1;
            }
            rs0 += __shfl_xor_sync(0xffffffffu, rs0, 1);
            rs0 += __shfl_xor_sync(0xffffffffu, rs0, 2);
            rs1 += __shfl_xor_sync(0xffffffffu, rs1, 1);
            rs1 += __shfl_xor_sync(0xffffffffu, rs1, 2);
            l0 = l0 * cor0 + rs0; l1 = l1 * cor1 + rs1;
            m0 = nm0; m1 = nm1;
        }
        __syncwarp();

        #pragma unroll
        for (int kb = 0; kb < 8; kb++) {
            uint32_t a[4];
            a[0] = __float_as_uint(Ks[wr + g    ][kb * 8 + t    ]);
            a[1] = __float_as_uint(Ks[wr + 8 + g][kb * 8 + t    ]);
            a[2] = __float_as_uint(Ks[wr + g    ][kb * 8 + t + 4]);
            a[3] = __float_as_uint(Ks[wr + 8 + g][kb * 8 + t + 4]);
            #pragma unroll
            for (int ni = 0; ni < 8; ni++) {
                uint32_t bb[2];
                bb[0] = __float_as_uint(Vs[kb * 8 + t    ][ni * 8 + g]);
                bb[1] = __float_as_uint(Vs[kb * 8 + t + 4][ni * 8 + g]);
                mma_tf32(o[ni], a, bb);
            }
        }
        __syncthreads();
    }

    float inv0 = 1.0f / l0, inv1 = 1.0f / l1;
    #pragma unroll
    for (int ni = 0; ni < 8; ni++) {
        int col = ni * 8 + 2 * t;
        float2 w0 = {o[ni][0] * inv0, o[ni][1] * inv0};
        float2 w1 = {o[ni][2] * inv1, o[ni][3] * inv1};
        *(float2*)(ctx + bh_off + (size_t)qg0 * DD + col) = w0;
        *(float2*)(ctx + bh_off + (size_t)qg1 * DD + col) = w1;
    }
}

// ---------------- launch ----------------
extern "C" void kernel_launch(void* const* d_in, const int* in_sizes, int n_in,
                              void* d_out, int out_size)
{
    const int*   ids    = (const int*)  d_in[0];
    const float* state  = (const float*)d_in[1];
    const float* wemb   = (const float*)d_in[2];
    const float* pemb   = (const float*)d_in[3];
    const float* ln_e_g = (const float*)d_in[4];
    const float* ln_e_b = (const float*)d_in[5];
    const float* Wq     = (const float*)d_in[6];
    const float* bq     = (const float*)d_in[7];
    const float* Wk     = (const float*)d_in[8];
    const float* bk     = (const float*)d_in[9];
    const float* Wv     = (const float*)d_in[10];
    const float* bv     = (const float*)d_in[11];
    const float* Wo     = (const float*)d_in[12];
    const float* bo     = (const float*)d_in[13];
    const float* ln_a_g = (const float*)d_in[14];
    const float* ln_a_b = (const float*)d_in[15];
    float* out = (float*)d_out;

    float *x, *q, *k, *v, *ctx, *hx;
    cudaGetSymbolAddress((void**)&x,   g_x);
    cudaGetSymbolAddress((void**)&q,   g_q);
    cudaGetSymbolAddress((void**)&k,   g_k);
    cudaGetSymbolAddress((void**)&v,   g_v);
    cudaGetSymbolAddress((void**)&ctx, g_ctx);
    cudaGetSymbolAddress((void**)&hx,  g_h);

    static int smem_set = 0;
    if (!smem_set) {
        cudaFuncSetAttribute(gemm_tf32_kernel<false>,
                             cudaFuncAttributeMaxDynamicSharedMemorySize, GSMEM);
        cudaFuncSetAttribute(gemm_tf32_kernel<true>,
                             cudaFuncAttributeMaxDynamicSharedMemorySize, GSMEM);
        smem_set = 1;
    }

    embed_ln_kernel<<<MTOK, 256>>>(ids, wemb, pemb, ln_e_g, ln_e_b, x);

    dim3 gqkv(DD / GBN, MTOK / GBM, 3);   // (6, 64, 3)
    gemm_tf32_kernel<false><<<gqkv, 256, GSMEM>>>(
        x, Wq, Wk, Wv, bq, bk, bv, nullptr, q, k, v);

    attn_mma_kernel<<<dim3(NCC * 4, HH, BB), 128>>>(q, k, v, ctx);

    dim3 go(DD / GBN, MTOK / GBM, 1);
    gemm_tf32_kernel<true><<<go, 256, GSMEM>>>(
        ctx, Wo, Wo, Wo, bo, bo, bo, x, hx, hx, hx);

    ln_kernel<<<MTOK, 256>>>(hx, ln_a_g, ln_a_b, out);

    long long tail = (long long)out_size - (long long)MTOK * DD;
    if (tail > 0) {
        cudaMemcpyAsync(out + (size_t)MTOK * DD, state,
                        (size_t)tail * sizeof(float),
                        cudaMemcpyDeviceToDevice);
    }
}

// round 5
// speedup vs baseline: 5.7424x; 1.5964x over previous
#include <cuda_runtime.h>
#include <cuda_bf16.h>
#include <math.h>
#include <stdint.h>

#define BB 2
#define SS 4096
#define DD 768
#define HH 12
#define DHH 64
#define W1C 256
#define NCC 16
#define MTOK (BB*SS)   // 8192
#define WSZ (DD*DD)

typedef __nv_bfloat16 bf16;

// ---------------- scratch (device globals; no allocation allowed) ----------------
__device__ __align__(16) float g_x [MTOK*DD];     // LN'd embeddings, fp32 (residual)
__device__ __align__(16) float g_h [MTOK*DD];     // pre-LN hidden, fp32
__device__ __align__(16) bf16  g_xb [MTOK*DD];    // bf16 copy of x
__device__ __align__(16) bf16  g_qb [MTOK*DD];
__device__ __align__(16) bf16  g_kb [MTOK*DD];
__device__ __align__(16) bf16  g_vb [MTOK*DD];
__device__ __align__(16) bf16  g_cb [MTOK*DD];    // attention context, bf16
__device__ __align__(16) bf16  g_wt [4*WSZ];      // transposed bf16 weights [w][n][k]

// ---------------- block reduction: sum + sumsq over 256 threads ----------------
__device__ __forceinline__ void block_reduce2(float& s, float& s2) {
    __shared__ float r1[8], r2[8];
    const unsigned mask = 0xffffffffu;
    #pragma unroll
    for (int o = 16; o > 0; o >>= 1) {
        s  += __shfl_xor_sync(mask, s,  o);
        s2 += __shfl_xor_sync(mask, s2, o);
    }
    int w = threadIdx.x >> 5, lane = threadIdx.x & 31;
    if (lane == 0) { r1[w] = s; r2[w] = s2; }
    __syncthreads();
    float a = 0.f, b = 0.f;
    #pragma unroll
    for (int i = 0; i < 8; i++) { a += r1[i]; b += r2[i]; }
    s = a; s2 = b;
}

// ---------------- embedding gather + layernorm (fp32 + bf16 outputs) ----------------
__global__ __launch_bounds__(256) void embed_ln_kernel(
    const int* __restrict__ ids, const float* __restrict__ wemb,
    const float* __restrict__ pemb, const float* __restrict__ g,
    const float* __restrict__ b, float* __restrict__ x, bf16* __restrict__ xb)
{
    int tok = blockIdx.x;
    int s_pos = tok & (SS - 1);
    int id = ids[tok];
    const float* we = wemb + (size_t)id * DD;
    const float* pe = pemb + (size_t)s_pos * DD;
    float v[3]; float sum = 0.f, sum2 = 0.f;
    #pragma unroll
    for (int i = 0; i < 3; i++) {
        int d = threadIdx.x + i * 256;
        v[i] = we[d] + pe[d];
        sum += v[i]; sum2 += v[i] * v[i];
    }
    block_reduce2(sum, sum2);
    float mean = sum * (1.0f / DD);
    float var  = sum2 * (1.0f / DD) - mean * mean;
    float rstd = rsqrtf(var + 1e-5f);
    float* row = x + (size_t)tok * DD;
    bf16*  rowb = xb + (size_t)tok * DD;
    #pragma unroll
    for (int i = 0; i < 3; i++) {
        int d = threadIdx.x + i * 256;
        float o = (v[i] - mean) * rstd * g[d] + b[d];
        row[d] = o;
        rowb[d] = __float2bfloat16(o);
    }
}

// ---------------- final layernorm ----------------
__global__ __launch_bounds__(256) void ln_kernel(
    const float* __restrict__ in, const float* __restrict__ g,
    const float* __restrict__ b, float* __restrict__ out)
{
    int tok = blockIdx.x;
    const float* row = in + (size_t)tok * DD;
    float v[3]; float sum = 0.f, sum2 = 0.f;
    #pragma unroll
    for (int i = 0; i < 3; i++) {
        int d = threadIdx.x + i * 256;
        v[i] = row[d];
        sum += v[i]; sum2 += v[i] * v[i];
    }
    block_reduce2(sum, sum2);
    float mean = sum * (1.0f / DD);
    float var  = sum2 * (1.0f / DD) - mean * mean;
    float rstd = rsqrtf(var + 1e-5f);
    float* orow = out + (size_t)tok * DD;
    #pragma unroll
    for (int i = 0; i < 3; i++) {
        int d = threadIdx.x + i * 256;
        orow[d] = (v[i] - mean) * rstd * g[d] + b[d];
    }
}

// ---------------- weight transpose + fp32->bf16 convert ----------------
// in: W[k][n] fp32 ; out: Wt[w][n][k] bf16
__global__ __launch_bounds__(256) void wtrans_kernel(
    const float* __restrict__ W0, const float* __restrict__ W1,
    const float* __restrict__ W2, const float* __restrict__ W3,
    bf16* __restrict__ wt)
{
    __shared__ float tile[32][33];
    int w = blockIdx.z;
    const float* W = (w == 0) ? W0 : (w == 1) ? W1 : (w == 2) ? W2 : W3;
    bf16* dst = wt + (size_t)w * WSZ;
    int k0 = blockIdx.y * 32, n0 = blockIdx.x * 32;
    int tx = threadIdx.x, ty = threadIdx.y;   // 32 x 8
    #pragma unroll
    for (int i = 0; i < 4; i++)
        tile[ty + i * 8][tx] = W[(size_t)(k0 + ty + i * 8) * DD + n0 + tx];
    __syncthreads();
    #pragma unroll
    for (int i = 0; i < 4; i++)
        dst[(size_t)(n0 + ty + i * 8) * DD + k0 + tx] = __float2bfloat16(tile[tx][ty + i * 8]);
}

// ---------------- async copy helpers ----------------
__device__ __forceinline__ void cp16(uint32_t smem, const void* gmem) {
    asm volatile("cp.async.cg.shared.global [%0], [%1], 16;\n" :: "r"(smem), "l"(gmem));
}
__device__ __forceinline__ void cp_commit() { asm volatile("cp.async.commit_group;\n"); }
template<int N>
__device__ __forceinline__ void cp_wait() { asm volatile("cp.async.wait_group %0;\n" :: "n"(N)); }

__device__ __forceinline__ void mma_bf16(float* c, const uint32_t* a, const uint32_t* b) {
    asm volatile(
        "mma.sync.aligned.m16n8k16.row.col.f32.bf16.bf16.f32 "
        "{%0,%1,%2,%3}, {%4,%5,%6,%7}, {%8,%9}, {%0,%1,%2,%3};\n"
        : "+f"(c[0]), "+f"(c[1]), "+f"(c[2]), "+f"(c[3])
        : "r"(a[0]), "r"(a[1]), "r"(a[2]), "r"(a[3]), "r"(b[0]), "r"(b[1]));
}

__device__ __forceinline__ uint32_t packbf(float x, float y) {
    __nv_bfloat162 h = __floats2bfloat162_rn(x, y);
    return *(uint32_t*)&h;
}

// ---------------- bf16 tensor-core GEMM, 128x128 tile, BK=32, 3-stage ----------------
#define GBM 128
#define GBN 128
#define GBK 32
#define GNIT (DD / GBK)   // 24
#define NSTG 3
#define KSTR 40           // smem row stride (bf16); bank(20g+t) conflict-free
#define A_ST (GBM * KSTR) // 5120 bf16
#define B_ST (GBN * KSTR) // 5120 bf16
#define GSMEM (NSTG * (A_ST + B_ST) * 2)  // 61440 bytes

extern __shared__ char dyn_smem[];

template<bool RES>
__global__ __launch_bounds__(256) void gemm_bf16_kernel(
    const bf16* __restrict__ A, const bf16* __restrict__ WtAll,
    const float* __restrict__ bias0, const float* __restrict__ bias1, const float* __restrict__ bias2,
    const float* __restrict__ res,
    bf16* __restrict__ C0, bf16* __restrict__ C1, bf16* __restrict__ C2,
    float* __restrict__ Cf)
{
    const int z = blockIdx.z;
    const bf16* Wt   = WtAll + (size_t)z * WSZ;
    const float* bias = (z == 0) ? bias0 : (z == 1) ? bias1 : bias2;
    bf16* Cb = (z == 0) ? C0 : (z == 1) ? C1 : C2;

    bf16* As = (bf16*)dyn_smem;            // [NSTG][GBM][KSTR]
    bf16* Bs = As + NSTG * A_ST;           // [NSTG][GBN][KSTR]

    const int tid = threadIdx.x;
    const int lane = tid & 31;
    const int wid = tid >> 5;
    const int g = lane >> 2;
    const int t = lane & 3;
    const int wm = (wid & 1) * 64;
    const int wn = (wid >> 1) * 32;
    const int rowBase = blockIdx.y * GBM;
    const int colBase = blockIdx.x * GBN;

    auto load_stage = [&](int st, int k0) {
        #pragma unroll
        for (int i = 0; i < 2; i++) {
            int idx = tid * 2 + i;            // 0..511
            int r = idx >> 2, ch = idx & 3;   // 128 rows x 4 chunks(8 bf16)
            const bf16* ga = A + (size_t)(rowBase + r) * DD + k0 + ch * 8;
            uint32_t sa = (uint32_t)__cvta_generic_to_shared(&As[st * A_ST + r * KSTR + ch * 8]);
            cp16(sa, ga);
            const bf16* gb = Wt + (size_t)(colBase + r) * DD + k0 + ch * 8;
            uint32_t sb = (uint32_t)__cvta_generic_to_shared(&Bs[st * B_ST + r * KSTR + ch * 8]);
            cp16(sb, gb);
        }
    };

    float acc[4][4][4];
    #pragma unroll
    for (int i = 0; i < 4; i++)
        #pragma unroll
        for (int j = 0; j < 4; j++)
            #pragma unroll
            for (int r = 0; r < 4; r++) acc[i][j][r] = 0.f;

    load_stage(0, 0);
    cp_commit();
    load_stage(1, GBK);
    cp_commit();

    for (int it = 0; it < GNIT; it++) {
        if (it + 2 < GNIT) load_stage((it + 2) % NSTG, (it + 2) * GBK);
        cp_commit();
        cp_wait<2>();
        __syncthreads();

        const bf16* Ast = As + (it % NSTG) * A_ST;
        const bf16* Bst = Bs + (it % NSTG) * B_ST;

        #pragma unroll
        for (int ks = 0; ks < 2; ks++) {
            int kb = ks * 16;
            uint32_t a[4][4];
            #pragma unroll
            for (int mi = 0; mi < 4; mi++) {
                int r = wm + mi * 16;
                a[mi][0] = *(const uint32_t*)&Ast[(r + g    ) * KSTR + kb + 2 * t    ];
                a[mi][1] = *(const uint32_t*)&Ast[(r + 8 + g) * KSTR + kb + 2 * t    ];
                a[mi][2] = *(const uint32_t*)&Ast[(r + g    ) * KSTR + kb + 2 * t + 8];
                a[mi][3] = *(const uint32_t*)&Ast[(r + 8 + g) * KSTR + kb + 2 * t + 8];
            }
            uint32_t b[4][2];
            #pragma unroll
            for (int ni = 0; ni < 4; ni++) {
                int n = wn + ni * 8 + g;
                b[ni][0] = *(const uint32_t*)&Bst[n * KSTR + kb + 2 * t    ];
                b[ni][1] = *(const uint32_t*)&Bst[n * KSTR + kb + 2 * t + 8];
            }
            #pragma unroll
            for (int mi = 0; mi < 4; mi++)
                #pragma unroll
                for (int ni = 0; ni < 4; ni++)
                    mma_bf16(acc[mi][ni], a[mi], b[ni]);
        }
        __syncthreads();
    }

    #pragma unroll
    for (int mi = 0; mi < 4; mi++) {
        #pragma unroll
        for (int rr = 0; rr < 2; rr++) {
            int row = rowBase + wm + mi * 16 + g + rr * 8;
            #pragma unroll
            for (int ni = 0; ni < 4; ni++) {
                int col = colBase + wn + ni * 8 + 2 * t;
                float c0 = acc[mi][ni][2 * rr + 0] + bias[col];
                float c1 = acc[mi][ni][2 * rr + 1] + bias[col + 1];
                if (RES) {
                    const float2 r2 = *(const float2*)&res[(size_t)row * DD + col];
                    c0 += r2.x; c1 += r2.y;
                    float2 o = {c0, c1};
                    *(float2*)&Cf[(size_t)row * DD + col] = o;
                } else {
                    __nv_bfloat162 h = __floats2bfloat162_rn(c0, c1);
                    *(__nv_bfloat162*)&Cb[(size_t)row * DD + col] = h;
                }
            }
        }
    }
}

// ---------------- banded attention, bf16 tensor-core flash, P in registers ----------------
#define ATSTR 72   // bank(4g+t) conflict-free

__global__ __launch_bounds__(128) void attn_mma_kernel(
    const bf16* __restrict__ q, const bf16* __restrict__ k,
    const bf16* __restrict__ v, bf16* __restrict__ ctx)
{
    __shared__ bf16 Ks[64][ATSTR];    // K tile (transient Q at start)
    __shared__ bf16 Vt[64][ATSTR];    // V tile TRANSPOSED: [d][key]

    const int tid = threadIdx.x;
    const int lane = tid & 31;
    const int wid = tid >> 5;
    const int g = lane >> 2;
    const int t = lane & 3;
    const int wr = wid * 16;

    const int sub = blockIdx.x & 3;
    const int c   = blockIdx.x >> 2;
    const int h   = blockIdx.y;
    const int b   = blockIdx.z;
    const int q0  = c * W1C + sub * 64;
    const size_t bh_off = (size_t)b * SS * DD + h * DHH;
    const float scale = 0.125f;

    // ---- Q tile into Ks (64 rows x 64 bf16 = 8 uint4/row) ----
    #pragma unroll
    for (int i = 0; i < 4; i++) {
        int idx = tid + i * 128;              // 0..511
        int r = idx >> 3, c8 = idx & 7;
        *(uint4*)&Ks[r][c8 * 8] =
            ((const uint4*)(q + bh_off + (size_t)(q0 + r) * DD))[c8];
    }
    __syncthreads();

    uint32_t qa[4][4];   // 4 k-tiles of 16 d
    #pragma unroll
    for (int j = 0; j < 4; j++) {
        qa[j][0] = *(const uint32_t*)&Ks[wr + g    ][j * 16 + 2 * t    ];
        qa[j][1] = *(const uint32_t*)&Ks[wr + 8 + g][j * 16 + 2 * t    ];
        qa[j][2] = *(const uint32_t*)&Ks[wr + g    ][j * 16 + 2 * t + 8];
        qa[j][3] = *(const uint32_t*)&Ks[wr + 8 + g][j * 16 + 2 * t + 8];
    }
    __syncthreads();

    float o[8][4];
    #pragma unroll
    for (int ni = 0; ni < 8; ni++)
        #pragma unroll
        for (int r = 0; r < 4; r++) o[ni][r] = 0.f;
    float m0 = -1e30f, m1 = -1e30f, l0 = 0.f, l1 = 0.f;

    const int qg0 = q0 + wr + g;
    const int qg1 = qg0 + 8;
    const int kstart = q0 - W1C;

    for (int jt = 0; jt < 9; jt++) {
        int kt0 = kstart + jt * 64;
        if (kt0 < 0 || kt0 >= SS) continue;

        // ---- K tile (row layout) + V tile (transposed) ----
        #pragma unroll
        for (int i = 0; i < 4; i++) {
            int idx = tid + i * 128;
            int r = idx >> 3, c8 = idx & 7;
            size_t roff = bh_off + (size_t)(kt0 + r) * DD;
            *(uint4*)&Ks[r][c8 * 8] = ((const uint4*)(k + roff))[c8];
            uint4 vv = ((const uint4*)(v + roff))[c8];
            const bf16* ve = (const bf16*)&vv;
            #pragma unroll
            for (int e = 0; e < 8; e++)
                Vt[c8 * 8 + e][r] = ve[e];
        }
        __syncthreads();

        // ---- S = Q K^T ----
        float s[8][4];
        #pragma unroll
        for (int ni = 0; ni < 8; ni++) {
            s[ni][0] = s[ni][1] = s[ni][2] = s[ni][3] = 0.f;
            #pragma unroll
            for (int j = 0; j < 4; j++) {
                uint32_t bb[2];
                bb[0] = *(const uint32_t*)&Ks[ni * 8 + g][j * 16 + 2 * t    ];
                bb[1] = *(const uint32_t*)&Ks[ni * 8 + g][j * 16 + 2 * t + 8];
                mma_bf16(s[ni], qa[j], bb);
            }
            s[ni][0] *= scale; s[ni][1] *= scale;
            s[ni][2] *= scale; s[ni][3] *= scale;
        }

        // ---- band mask (boundary tiles only) ----
        if (jt == 0 || jt == 8) {
            #pragma unroll
            for (int ni = 0; ni < 8; ni++) {
                int kg = kt0 + ni * 8 + 2 * t;
                if (kg < qg0 - W1C || kg > qg0 + W1C) s[ni][0] = -1e30f;
                if (kg + 1 < qg0 - W1C || kg + 1 > qg0 + W1C) s[ni][1] = -1e30f;
                if (kg < qg1 - W1C || kg > qg1 + W1C) s[ni][2] = -1e30f;
                if (kg + 1 < qg1 - W1C || kg + 1 > qg1 + W1C) s[ni][3] = -1e30f;
            }
        }

        // ---- online softmax (P stays in s[], fp32) ----
        {
            float mx0 = -1e30f, mx1 = -1e30f;
            #pragma unroll
            for (int ni = 0; ni < 8; ni++) {
                mx0 = fmaxf(mx0, fmaxf(s[ni][0], s[ni][1]));
                mx1 = fmaxf(mx1, fmaxf(s[ni][2], s[ni][3]));
            }
            mx0 = fmaxf(mx0, __shfl_xor_sync(0xffffffffu, mx0, 1));
            mx0 = fmaxf(mx0, __shfl_xor_sync(0xffffffffu, mx0, 2));
            mx1 = fmaxf(mx1, __shfl_xor_sync(0xffffffffu, mx1, 1));
            mx1 = fmaxf(mx1, __shfl_xor_sync(0xffffffffu, mx1, 2));
            float nm0 = fmaxf(m0, mx0), nm1 = fmaxf(m1, mx1);
            float cor0 = __expf(m0 - nm0), cor1 = __expf(m1 - nm1);
            float rs0 = 0.f, rs1 = 0.f;
            #pragma unroll
            for (int ni = 0; ni < 8; ni++) {
                s[ni][0] = __expf(s[ni][0] - nm0);
                s[ni][1] = __expf(s[ni][1] - nm0);
                s[ni][2] = __expf(s[ni][2] - nm1);
                s[ni][3] = __expf(s[ni][3] - nm1);
                rs0 += s[ni][0] + s[ni][1];
                rs1 += s[ni][2] + s[ni][3];
                o[ni][0] *= cor0; o[ni][1] *= cor0;
                o[ni][2] *= cor1; o[ni][3] *= cor1;
            }
            rs0 += __shfl_xor_sync(0xffffffffu, rs0, 1);
            rs0 += __shfl_xor_sync(0xffffffffu, rs0, 2);
            rs1 += __shfl_xor_sync(0xffffffffu, rs1, 1);
            rs1 += __shfl_xor_sync(0xffffffffu, rs1, 2);
            l0 = l0 * cor0 + rs0; l1 = l1 * cor1 + rs1;
            m0 = nm0; m1 = nm1;
        }

        // ---- O += P V  (P packed from registers) ----
        #pragma unroll
        for (int j = 0; j < 4; j++) {
            uint32_t a[4];
            a[0] = packbf(s[2*j    ][0], s[2*j    ][1]);
            a[1] = packbf(s[2*j    ][2], s[2*j    ][3]);
            a[2] = packbf(s[2*j + 1][0], s[2*j + 1][1]);
            a[3] = packbf(s[2*j + 1][2], s[2*j + 1][3]);
            #pragma unroll
            for (int ni = 0; ni < 8; ni++) {
                uint32_t bb[2];
                bb[0] = *(const uint32_t*)&Vt[ni * 8 + g][j * 16 + 2 * t    ];
                bb[1] = *(const uint32_t*)&Vt[ni * 8 + g][j * 16 + 2 * t + 8];
                mma_bf16(o[ni], a, bb);
            }
        }
        __syncthreads();
    }

    // ---- epilogue ----
    float inv0 = 1.0f / l0, inv1 = 1.0f / l1;
    #pragma unroll
    for (int ni = 0; ni < 8; ni++) {
        int col = ni * 8 + 2 * t;
        __nv_bfloat162 w0 = __floats2bfloat162_rn(o[ni][0] * inv0, o[ni][1] * inv0);
        __nv_bfloat162 w1 = __floats2bfloat162_rn(o[ni][2] * inv1, o[ni][3] * inv1);
        *(__nv_bfloat162*)(ctx + bh_off + (size_t)qg0 * DD + col) = w0;
        *(__nv_bfloat162*)(ctx + bh_off + (size_t)qg1 * DD + col) = w1;
    }
}

// ---------------- launch ----------------
extern "C" void kernel_launch(void* const* d_in, const int* in_sizes, int n_in,
                              void* d_out, int out_size)
{
    const int*   ids    = (const int*)  d_in[0];
    const float* state  = (const float*)d_in[1];
    const float* wemb   = (const float*)d_in[2];
    const float* pemb   = (const float*)d_in[3];
    const float* ln_e_g = (const float*)d_in[4];
    const float* ln_e_b = (const float*)d_in[5];
    const float* Wq     = (const float*)d_in[6];
    const float* bq     = (const float*)d_in[7];
    const float* Wk     = (const float*)d_in[8];
    const float* bk     = (const float*)d_in[9];
    const float* Wv     = (const float*)d_in[10];
    const float* bv     = (const float*)d_in[11];
    const float* Wo     = (const float*)d_in[12];
    const float* bo     = (const float*)d_in[13];
    const float* ln_a_g = (const float*)d_in[14];
    const float* ln_a_b = (const float*)d_in[15];
    float* out = (float*)d_out;

    float *x, *hx;  bf16 *xb, *qb, *kb, *vb, *cb, *wt;
    cudaGetSymbolAddress((void**)&x,  g_x);
    cudaGetSymbolAddress((void**)&hx, g_h);
    cudaGetSymbolAddress((void**)&xb, g_xb);
    cudaGetSymbolAddress((void**)&qb, g_qb);
    cudaGetSymbolAddress((void**)&kb, g_kb);
    cudaGetSymbolAddress((void**)&vb, g_vb);
    cudaGetSymbolAddress((void**)&cb, g_cb);
    cudaGetSymbolAddress((void**)&wt, g_wt);

    static int smem_set = 0;
    if (!smem_set) {
        cudaFuncSetAttribute(gemm_bf16_kernel<false>,
                             cudaFuncAttributeMaxDynamicSharedMemorySize, GSMEM);
        cudaFuncSetAttribute(gemm_bf16_kernel<true>,
                             cudaFuncAttributeMaxDynamicSharedMemorySize, GSMEM);
        smem_set = 1;
    }

    embed_ln_kernel<<<MTOK, 256>>>(ids, wemb, pemb, ln_e_g, ln_e_b, x, xb);
    wtrans_kernel<<<dim3(24, 24, 4), dim3(32, 8)>>>(Wq, Wk, Wv, Wo, wt);

    dim3 gqkv(DD / GBN, MTOK / GBM, 3);   // (6, 64, 3)
    gemm_bf16_kernel<false><<<gqkv, 256, GSMEM>>>(
        xb, wt, bq, bk, bv, nullptr, qb, kb, vb, nullptr);

    attn_mma_kernel<<<dim3(NCC * 4, HH, BB), 128>>>(qb, kb, vb, cb);

    dim3 go(DD / GBN, MTOK / GBM, 1);
    gemm_bf16_kernel<true><<<go, 256, GSMEM>>>(
        cb, wt + 3 * (size_t)WSZ, bo, bo, bo, x, nullptr, nullptr, nullptr, hx);

    ln_kernel<<<MTOK, 256>>>(hx, ln_a_g, ln_a_b, out);

    long long tail = (long long)out_size - (long long)MTOK * DD;
    if (tail > 0) {
        cudaMemcpyAsync(out + (size_t)MTOK * DD, state,
                        (size_t)tail * sizeof(float),
                        cudaMemcpyDeviceToDevice);
    }
}

// round 6
// speedup vs baseline: 6.4833x; 1.1290x over previous
#include <cuda_runtime.h>
#include <cuda_bf16.h>
#include <math.h>
#include <stdint.h>

#define BB 2
#define SS 4096
#define DD 768
#define HH 12
#define DHH 64
#define W1C 256
#define NCC 16
#define MTOK (BB*SS)   // 8192
#define WSZ (DD*DD)

typedef __nv_bfloat16 bf16;

// ---------------- scratch (device globals; no allocation allowed) ----------------
__device__ __align__(16) float g_x [MTOK*DD];
__device__ __align__(16) float g_h [MTOK*DD];
__device__ __align__(16) bf16  g_xb [MTOK*DD];
__device__ __align__(16) bf16  g_qb [MTOK*DD];
__device__ __align__(16) bf16  g_kb [MTOK*DD];
__device__ __align__(16) bf16  g_vb [MTOK*DD];
__device__ __align__(16) bf16  g_cb [MTOK*DD];
__device__ __align__(16) bf16  g_wt [4*WSZ];

// ---------------- block reduction ----------------
__device__ __forceinline__ void block_reduce2(float& s, float& s2) {
    __shared__ float r1[8], r2[8];
    const unsigned mask = 0xffffffffu;
    #pragma unroll
    for (int o = 16; o > 0; o >>= 1) {
        s  += __shfl_xor_sync(mask, s,  o);
        s2 += __shfl_xor_sync(mask, s2, o);
    }
    int w = threadIdx.x >> 5, lane = threadIdx.x & 31;
    if (lane == 0) { r1[w] = s; r2[w] = s2; }
    __syncthreads();
    float a = 0.f, b = 0.f;
    #pragma unroll
    for (int i = 0; i < 8; i++) { a += r1[i]; b += r2[i]; }
    s = a; s2 = b;
}

// ---------------- embedding gather + layernorm ----------------
__global__ __launch_bounds__(256) void embed_ln_kernel(
    const int* __restrict__ ids, const float* __restrict__ wemb,
    const float* __restrict__ pemb, const float* __restrict__ g,
    const float* __restrict__ b, float* __restrict__ x, bf16* __restrict__ xb)
{
    int tok = blockIdx.x;
    int s_pos = tok & (SS - 1);
    int id = ids[tok];
    const float* we = wemb + (size_t)id * DD;
    const float* pe = pemb + (size_t)s_pos * DD;
    float v[3]; float sum = 0.f, sum2 = 0.f;
    #pragma unroll
    for (int i = 0; i < 3; i++) {
        int d = threadIdx.x + i * 256;
        v[i] = we[d] + pe[d];
        sum += v[i]; sum2 += v[i] * v[i];
    }
    block_reduce2(sum, sum2);
    float mean = sum * (1.0f / DD);
    float var  = sum2 * (1.0f / DD) - mean * mean;
    float rstd = rsqrtf(var + 1e-5f);
    float* row = x + (size_t)tok * DD;
    bf16*  rowb = xb + (size_t)tok * DD;
    #pragma unroll
    for (int i = 0; i < 3; i++) {
        int d = threadIdx.x + i * 256;
        float o = (v[i] - mean) * rstd * g[d] + b[d];
        row[d] = o;
        rowb[d] = __float2bfloat16(o);
    }
}

// ---------------- final layernorm ----------------
__global__ __launch_bounds__(256) void ln_kernel(
    const float* __restrict__ in, const float* __restrict__ g,
    const float* __restrict__ b, float* __restrict__ out)
{
    int tok = blockIdx.x;
    const float* row = in + (size_t)tok * DD;
    float v[3]; float sum = 0.f, sum2 = 0.f;
    #pragma unroll
    for (int i = 0; i < 3; i++) {
        int d = threadIdx.x + i * 256;
        v[i] = row[d];
        sum += v[i]; sum2 += v[i] * v[i];
    }
    block_reduce2(sum, sum2);
    float mean = sum * (1.0f / DD);
    float var  = sum2 * (1.0f / DD) - mean * mean;
    float rstd = rsqrtf(var + 1e-5f);
    float* orow = out + (size_t)tok * DD;
    #pragma unroll
    for (int i = 0; i < 3; i++) {
        int d = threadIdx.x + i * 256;
        orow[d] = (v[i] - mean) * rstd * g[d] + b[d];
    }
}

// ---------------- weight transpose + convert ----------------
__global__ __launch_bounds__(256) void wtrans_kernel(
    const float* __restrict__ W0, const float* __restrict__ W1,
    const float* __restrict__ W2, const float* __restrict__ W3,
    bf16* __restrict__ wt)
{
    __shared__ float tile[32][33];
    int w = blockIdx.z;
    const float* W = (w == 0) ? W0 : (w == 1) ? W1 : (w == 2) ? W2 : W3;
    bf16* dst = wt + (size_t)w * WSZ;
    int k0 = blockIdx.y * 32, n0 = blockIdx.x * 32;
    int tx = threadIdx.x, ty = threadIdx.y;
    #pragma unroll
    for (int i = 0; i < 4; i++)
        tile[ty + i * 8][tx] = W[(size_t)(k0 + ty + i * 8) * DD + n0 + tx];
    __syncthreads();
    #pragma unroll
    for (int i = 0; i < 4; i++)
        dst[(size_t)(n0 + ty + i * 8) * DD + k0 + tx] = __float2bfloat16(tile[tx][ty + i * 8]);
}

// ---------------- async copy + mma + ldmatrix helpers ----------------
__device__ __forceinline__ void cp16(uint32_t smem, const void* gmem) {
    asm volatile("cp.async.cg.shared.global [%0], [%1], 16;\n" :: "r"(smem), "l"(gmem));
}
__device__ __forceinline__ void cp_commit() { asm volatile("cp.async.commit_group;\n"); }
template<int N>
__device__ __forceinline__ void cp_wait() { asm volatile("cp.async.wait_group %0;\n" :: "n"(N)); }

__device__ __forceinline__ void mma_bf16(float* c, const uint32_t* a, const uint32_t* b) {
    asm volatile(
        "mma.sync.aligned.m16n8k16.row.col.f32.bf16.bf16.f32 "
        "{%0,%1,%2,%3}, {%4,%5,%6,%7}, {%8,%9}, {%0,%1,%2,%3};\n"
        : "+f"(c[0]), "+f"(c[1]), "+f"(c[2]), "+f"(c[3])
        : "r"(a[0]), "r"(a[1]), "r"(a[2]), "r"(a[3]), "r"(b[0]), "r"(b[1]));
}

__device__ __forceinline__ uint32_t packbf(float x, float y) {
    __nv_bfloat162 h = __floats2bfloat162_rn(x, y);
    return *(uint32_t*)&h;
}

__device__ __forceinline__ void ldsm_x4(uint32_t& r0, uint32_t& r1, uint32_t& r2, uint32_t& r3, uint32_t addr) {
    asm volatile("ldmatrix.sync.aligned.m8n8.x4.shared.b16 {%0,%1,%2,%3}, [%4];\n"
        : "=r"(r0), "=r"(r1), "=r"(r2), "=r"(r3) : "r"(addr));
}
__device__ __forceinline__ void ldsm_x4_t(uint32_t& r0, uint32_t& r1, uint32_t& r2, uint32_t& r3, uint32_t addr) {
    asm volatile("ldmatrix.sync.aligned.m8n8.x4.trans.shared.b16 {%0,%1,%2,%3}, [%4];\n"
        : "=r"(r0), "=r"(r1), "=r"(r2), "=r"(r3) : "r"(addr));
}

// ---------------- bf16 tensor-core GEMM (unchanged from R5) ----------------
#define GBM 128
#define GBN 128
#define GBK 32
#define GNIT (DD / GBK)   // 24
#define NSTG 3
#define KSTR 40
#define A_ST (GBM * KSTR)
#define B_ST (GBN * KSTR)
#define GSMEM (NSTG * (A_ST + B_ST) * 2)  // 61440 bytes

extern __shared__ char dyn_smem[];

template<bool RES>
__global__ __launch_bounds__(256) void gemm_bf16_kernel(
    const bf16* __restrict__ A, const bf16* __restrict__ WtAll,
    const float* __restrict__ bias0, const float* __restrict__ bias1, const float* __restrict__ bias2,
    const float* __restrict__ res,
    bf16* __restrict__ C0, bf16* __restrict__ C1, bf16* __restrict__ C2,
    float* __restrict__ Cf)
{
    const int z = blockIdx.z;
    const bf16* Wt   = WtAll + (size_t)z * WSZ;
    const float* bias = (z == 0) ? bias0 : (z == 1) ? bias1 : bias2;
    bf16* Cb = (z == 0) ? C0 : (z == 1) ? C1 : C2;

    bf16* As = (bf16*)dyn_smem;
    bf16* Bs = As + NSTG * A_ST;

    const int tid = threadIdx.x;
    const int lane = tid & 31;
    const int wid = tid >> 5;
    const int g = lane >> 2;
    const int t = lane & 3;
    const int wm = (wid & 1) * 64;
    const int wn = (wid >> 1) * 32;
    const int rowBase = blockIdx.y * GBM;
    const int colBase = blockIdx.x * GBN;

    auto load_stage = [&](int st, int k0) {
        #pragma unroll
        for (int i = 0; i < 2; i++) {
            int idx = tid * 2 + i;
            int r = idx >> 2, ch = idx & 3;
            const bf16* ga = A + (size_t)(rowBase + r) * DD + k0 + ch * 8;
            uint32_t sa = (uint32_t)__cvta_generic_to_shared(&As[st * A_ST + r * KSTR + ch * 8]);
            cp16(sa, ga);
            const bf16* gb = Wt + (size_t)(colBase + r) * DD + k0 + ch * 8;
            uint32_t sb = (uint32_t)__cvta_generic_to_shared(&Bs[st * B_ST + r * KSTR + ch * 8]);
            cp16(sb, gb);
        }
    };

    float acc[4][4][4];
    #pragma unroll
    for (int i = 0; i < 4; i++)
        #pragma unroll
        for (int j = 0; j < 4; j++)
            #pragma unroll
            for (int r = 0; r < 4; r++) acc[i][j][r] = 0.f;

    load_stage(0, 0);
    cp_commit();
    load_stage(1, GBK);
    cp_commit();

    for (int it = 0; it < GNIT; it++) {
        if (it + 2 < GNIT) load_stage((it + 2) % NSTG, (it + 2) * GBK);
        cp_commit();
        cp_wait<2>();
        __syncthreads();

        const bf16* Ast = As + (it % NSTG) * A_ST;
        const bf16* Bst = Bs + (it % NSTG) * B_ST;

        #pragma unroll
        for (int ks = 0; ks < 2; ks++) {
            int kb = ks * 16;
            uint32_t a[4][4];
            #pragma unroll
            for (int mi = 0; mi < 4; mi++) {
                int r = wm + mi * 16;
                a[mi][0] = *(const uint32_t*)&Ast[(r + g    ) * KSTR + kb + 2 * t    ];
                a[mi][1] = *(const uint32_t*)&Ast[(r + 8 + g) * KSTR + kb + 2 * t    ];
                a[mi][2] = *(const uint32_t*)&Ast[(r + g    ) * KSTR + kb + 2 * t + 8];
                a[mi][3] = *(const uint32_t*)&Ast[(r + 8 + g) * KSTR + kb + 2 * t + 8];
            }
            uint32_t b[4][2];
            #pragma unroll
            for (int ni = 0; ni < 4; ni++) {
                int n = wn + ni * 8 + g;
                b[ni][0] = *(const uint32_t*)&Bst[n * KSTR + kb + 2 * t    ];
                b[ni][1] = *(const uint32_t*)&Bst[n * KSTR + kb + 2 * t + 8];
            }
            #pragma unroll
            for (int mi = 0; mi < 4; mi++)
                #pragma unroll
                for (int ni = 0; ni < 4; ni++)
                    mma_bf16(acc[mi][ni], a[mi], b[ni]);
        }
        __syncthreads();
    }

    #pragma unroll
    for (int mi = 0; mi < 4; mi++) {
        #pragma unroll
        for (int rr = 0; rr < 2; rr++) {
            int row = rowBase + wm + mi * 16 + g + rr * 8;
            #pragma unroll
            for (int ni = 0; ni < 4; ni++) {
                int col = colBase + wn + ni * 8 + 2 * t;
                float c0 = acc[mi][ni][2 * rr + 0] + bias[col];
                float c1 = acc[mi][ni][2 * rr + 1] + bias[col + 1];
                if (RES) {
                    const float2 r2 = *(const float2*)&res[(size_t)row * DD + col];
                    c0 += r2.x; c1 += r2.y;
                    float2 o = {c0, c1};
                    *(float2*)&Cf[(size_t)row * DD + col] = o;
                } else {
                    __nv_bfloat162 h = __floats2bfloat162_rn(c0, c1);
                    *(__nv_bfloat162*)&Cb[(size_t)row * DD + col] = h;
                }
            }
        }
    }
}

// ---------------- banded attention: 128-query blocks, ldmatrix, cp.async ----------------
#define ATS 72   // bf16 row stride; 144B => ldmatrix rows hit disjoint 4-bank groups

__global__ __launch_bounds__(256) void attn_mma_kernel(
    const bf16* __restrict__ q, const bf16* __restrict__ k,
    const bf16* __restrict__ v, bf16* __restrict__ ctx)
{
    __shared__ bf16 Ks[2][64][ATS];
    __shared__ bf16 Vs[2][64][ATS];   // row-major [key][d]

    const int tid = threadIdx.x;
    const int lane = tid & 31;
    const int wid = tid >> 5;      // 0..7
    const int g = lane >> 2;
    const int t = lane & 3;
    const int wr = wid * 16;

    const int q0 = blockIdx.x * 128;
    const int h  = blockIdx.y;
    const int b  = blockIdx.z;
    const size_t bh_off = (size_t)b * SS * DD + h * DHH;
    const float scale = 0.125f;

    const int qg0 = q0 + wr + g;
    const int qg1 = qg0 + 8;

    // ---- Q fragments straight from gmem ----
    uint32_t qa[4][4];
    {
        const bf16* r0p = q + bh_off + (size_t)qg0 * DD;
        const bf16* r1p = q + bh_off + (size_t)qg1 * DD;
        #pragma unroll
        for (int j = 0; j < 4; j++) {
            qa[j][0] = *(const uint32_t*)&r0p[j * 16 + 2 * t    ];
            qa[j][1] = *(const uint32_t*)&r1p[j * 16 + 2 * t    ];
            qa[j][2] = *(const uint32_t*)&r0p[j * 16 + 2 * t + 8];
            qa[j][3] = *(const uint32_t*)&r1p[j * 16 + 2 * t + 8];
        }
    }

    const int kstart = q0 - 2 * 128;  // q0 - 256
    const int jlo = (q0 < 256) ? (256 - q0) / 64 : 0;
    const int jhi = min(9, (SS + 192 - q0) / 64);   // kt0 <= SS-64

    auto prefetch = [&](int jt, int bu) {
        int kt0 = kstart + jt * 64;
        #pragma unroll
        for (int i = 0; i < 2; i++) {
            int idx = tid + i * 256;          // 0..511
            int r = idx >> 3, c8 = idx & 7;
            const bf16* base = k + bh_off + (size_t)(kt0 + r) * DD + c8 * 8;
            cp16((uint32_t)__cvta_generic_to_shared(&Ks[bu][r][c8 * 8]), base);
            const bf16* basev = v + bh_off + (size_t)(kt0 + r) * DD + c8 * 8;
            cp16((uint32_t)__cvta_generic_to_shared(&Vs[bu][r][c8 * 8]), basev);
        }
    };

    float o[8][4];
    #pragma unroll
    for (int ni = 0; ni < 8; ni++)
        #pragma unroll
        for (int r = 0; r < 4; r++) o[ni][r] = 0.f;
    float m0 = -1e30f, m1 = -1e30f, l0 = 0.f, l1 = 0.f;

    prefetch(jlo, 0);
    cp_commit();

    for (int jt = jlo; jt <= jhi; jt++) {
        const int bu = (jt - jlo) & 1;
        if (jt < jhi) prefetch(jt + 1, bu ^ 1);
        cp_commit();
        cp_wait<1>();
        __syncthreads();

        const int kt0 = kstart + jt * 64;

        // ---- S = Q K^T via ldmatrix.x4 on K rows ----
        float s[8][4];
        #pragma unroll
        for (int ni = 0; ni < 8; ni++)
            s[ni][0] = s[ni][1] = s[ni][2] = s[ni][3] = 0.f;

        #pragma unroll
        for (int nn = 0; nn < 4; nn++) {     // key-pair groups: keys nn*16..+15
            #pragma unroll
            for (int j = 0; j < 4; j++) {    // d chunks of 16
                uint32_t r0, r1, r2, r3;
                uint32_t addr = (uint32_t)__cvta_generic_to_shared(
                    &Ks[bu][nn * 16 + (lane & 15)][j * 16 + (lane >> 4) * 8]);
                ldsm_x4(r0, r1, r2, r3, addr);
                uint32_t b0[2] = {r0, r2};
                uint32_t b1[2] = {r1, r3};
                mma_bf16(s[2 * nn    ], qa[j], b0);
                mma_bf16(s[2 * nn + 1], qa[j], b1);
            }
        }
        #pragma unroll
        for (int ni = 0; ni < 8; ni++) {
            s[ni][0] *= scale; s[ni][1] *= scale;
            s[ni][2] *= scale; s[ni][3] *= scale;
        }

        // ---- band mask (outer tiles only) ----
        if (jt <= 1 || jt >= 8) {
            #pragma unroll
            for (int ni = 0; ni < 8; ni++) {
                int kg = kt0 + ni * 8 + 2 * t;
                if (kg < qg0 - W1C || kg > qg0 + W1C) s[ni][0] = -1e30f;
                if (kg + 1 < qg0 - W1C || kg + 1 > qg0 + W1C) s[ni][1] = -1e30f;
                if (kg < qg1 - W1C || kg > qg1 + W1C) s[ni][2] = -1e30f;
                if (kg + 1 < qg1 - W1C || kg + 1 > qg1 + W1C) s[ni][3] = -1e30f;
            }
        }

        // ---- online softmax ----
        {
            float mx0 = -1e30f, mx1 = -1e30f;
            #pragma unroll
            for (int ni = 0; ni < 8; ni++) {
                mx0 = fmaxf(mx0, fmaxf(s[ni][0], s[ni][1]));
                mx1 = fmaxf(mx1, fmaxf(s[ni][2], s[ni][3]));
            }
            mx0 = fmaxf(mx0, __shfl_xor_sync(0xffffffffu, mx0, 1));
            mx0 = fmaxf(mx0, __shfl_xor_sync(0xffffffffu, mx0, 2));
            mx1 = fmaxf(mx1, __shfl_xor_sync(0xffffffffu, mx1, 1));
            mx1 = fmaxf(mx1, __shfl_xor_sync(0xffffffffu, mx1, 2));
            float nm0 = fmaxf(m0, mx0), nm1 = fmaxf(m1, mx1);
            float cor0 = __expf(m0 - nm0), cor1 = __expf(m1 - nm1);
            float rs0 = 0.f, rs1 = 0.f;
            #pragma unroll
            for (int ni = 0; ni < 8; ni++) {
                s[ni][0] = __expf(s[ni][0] - nm0);
                s[ni][1] = __expf(s[ni][1] - nm0);
                s[ni][2] = __expf(s[ni][2] - nm1);
                s[ni][3] = __expf(s[ni][3] - nm1);
                rs0 += s[ni][0] + s[ni][1];
                rs1 += s[ni][2] + s[ni][3];
                o[ni][0] *= cor0; o[ni][1] *= cor0;
                o[ni][2] *= cor1; o[ni][3] *= cor1;
            }
            rs0 += __shfl_xor_sync(0xffffffffu, rs0, 1);
            rs0 += __shfl_xor_sync(0xffffffffu, rs0, 2);
            rs1 += __shfl_xor_sync(0xffffffffu, rs1, 1);
            rs1 += __shfl_xor_sync(0xffffffffu, rs1, 2);
            l0 = l0 * cor0 + rs0; l1 = l1 * cor1 + rs1;
            m0 = nm0; m1 = nm1;
        }

        // ---- O += P V via ldmatrix.x4.trans on row-major V ----
        #pragma unroll
        for (int j = 0; j < 4; j++) {        // key chunks of 16
            uint32_t a[4];
            a[0] = packbf(s[2 * j    ][0], s[2 * j    ][1]);
            a[1] = packbf(s[2 * j    ][2], s[2 * j    ][3]);
            a[2] = packbf(s[2 * j + 1][0], s[2 * j + 1][1]);
            a[3] = packbf(s[2 * j + 1][2], s[2 * j + 1][3]);
            #pragma unroll
            for (int nn = 0; nn < 4; nn++) { // d-pair groups: d nn*16..+15
                uint32_t r0, r1, r2, r3;
                uint32_t addr = (uint32_t)__cvta_generic_to_shared(
                    &Vs[bu][j * 16 + (lane & 15)][nn * 16 + (lane >> 4) * 8]);
                ldsm_x4_t(r0, r1, r2, r3, addr);
                uint32_t b0[2] = {r0, r1};
                uint32_t b1[2] = {r2, r3};
                mma_bf16(o[2 * nn    ], a, b0);
                mma_bf16(o[2 * nn + 1], a, b1);
            }
        }
        __syncthreads();
    }

    // ---- epilogue ----
    float inv0 = 1.0f / l0, inv1 = 1.0f / l1;
    #pragma unroll
    for (int ni = 0; ni < 8; ni++) {
        int col = ni * 8 + 2 * t;
        __nv_bfloat162 w0 = __floats2bfloat162_rn(o[ni][0] * inv0, o[ni][1] * inv0);
        __nv_bfloat162 w1 = __floats2bfloat162_rn(o[ni][2] * inv1, o[ni][3] * inv1);
        *(__nv_bfloat162*)(ctx + bh_off + (size_t)qg0 * DD + col) = w0;
        *(__nv_bfloat162*)(ctx + bh_off + (size_t)qg1 * DD + col) = w1;
    }
}

// ---------------- launch ----------------
extern "C" void kernel_launch(void* const* d_in, const int* in_sizes, int n_in,
                              void* d_out, int out_size)
{
    const int*   ids    = (const int*)  d_in[0];
    const float* state  = (const float*)d_in[1];
    const float* wemb   = (const float*)d_in[2];
    const float* pemb   = (const float*)d_in[3];
    const float* ln_e_g = (const float*)d_in[4];
    const float* ln_e_b = (const float*)d_in[5];
    const float* Wq     = (const float*)d_in[6];
    const float* bq     = (const float*)d_in[7];
    const float* Wk     = (const float*)d_in[8];
    const float* bk     = (const float*)d_in[9];
    const float* Wv     = (const float*)d_in[10];
    const float* bv     = (const float*)d_in[11];
    const float* Wo     = (const float*)d_in[12];
    const float* bo     = (const float*)d_in[13];
    const float* ln_a_g = (const float*)d_in[14];
    const float* ln_a_b = (const float*)d_in[15];
    float* out = (float*)d_out;

    float *x, *hx;  bf16 *xb, *qb, *kb, *vb, *cb, *wt;
    cudaGetSymbolAddress((void**)&x,  g_x);
    cudaGetSymbolAddress((void**)&hx, g_h);
    cudaGetSymbolAddress((void**)&xb, g_xb);
    cudaGetSymbolAddress((void**)&qb, g_qb);
    cudaGetSymbolAddress((void**)&kb, g_kb);
    cudaGetSymbolAddress((void**)&vb, g_vb);
    cudaGetSymbolAddress((void**)&cb, g_cb);
    cudaGetSymbolAddress((void**)&wt, g_wt);

    static int smem_set = 0;
    if (!smem_set) {
        cudaFuncSetAttribute(gemm_bf16_kernel<false>,
                             cudaFuncAttributeMaxDynamicSharedMemorySize, GSMEM);
        cudaFuncSetAttribute(gemm_bf16_kernel<true>,
                             cudaFuncAttributeMaxDynamicSharedMemorySize, GSMEM);
        smem_set = 1;
    }

    embed_ln_kernel<<<MTOK, 256>>>(ids, wemb, pemb, ln_e_g, ln_e_b, x, xb);
    wtrans_kernel<<<dim3(24, 24, 4), dim3(32, 8)>>>(Wq, Wk, Wv, Wo, wt);

    dim3 gqkv(DD / GBN, MTOK / GBM, 3);
    gemm_bf16_kernel<false><<<gqkv, 256, GSMEM>>>(
        xb, wt, bq, bk, bv, nullptr, qb, kb, vb, nullptr);

    attn_mma_kernel<<<dim3(SS / 128, HH, BB), 256>>>(qb, kb, vb, cb);

    dim3 go(DD / GBN, MTOK / GBM, 1);
    gemm_bf16_kernel<true><<<go, 256, GSMEM>>>(
        cb, wt + 3 * (size_t)WSZ, bo, bo, bo, x, nullptr, nullptr, nullptr, hx);

    ln_kernel<<<MTOK, 256>>>(hx, ln_a_g, ln_a_b, out);

    long long tail = (long long)out_size - (long long)MTOK * DD;
    if (tail > 0) {
        cudaMemcpyAsync(out + (size_t)MTOK * DD, state,
                        (size_t)tail * sizeof(float),
                        cudaMemcpyDeviceToDevice);
    }
}